// round 10
// baseline (speedup 1.0000x reference)
#include <cuda_runtime.h>
#include <cstdint>

#define BH   32
#define LTOT 4096
#define DD   128
#define MM   640
#define TM   64
#define NMT  (MM/TM)    // 10
#define TLK  128        // k1 l-chunk
#define NCH  (LTOT/TLK) // 32
#define NSPL 8
#define CHK  (NCH/NSPL) // 4
#define TL2  128
#define NLT2 (LTOT/TL2) // 32
#define LDP  136        // permuted tiles (K, P, phiT): 136 mod 32 == 8 (LDS.64 bijective)
#define LDV  140        // plain V tile: 140 mod 32 == 12 (GEMM-B b-frag bijective)
#define LDX2 140
#define PT2  68

#define N4CTX (BH*MM*DD/4)  // 655360
#define N4KS  (BH*MM/4)     // 5120

#define INV_SSD  0.2973017787506803f
#define INV2SQD  0.04419417382415922f
#define CADD    -3.2306341575510305f

__device__ float g_ctx[(size_t)BH * MM * DD];
__device__ float g_ksum[BH * MM];
__device__ float g_ctx_part[NSPL][(size_t)BH * MM * DD];   // 84 MB
__device__ float g_ksum_part[NSPL][BH * MM];

__device__ __forceinline__ float to_tf32(float x) {
    uint32_t u;
    asm("cvt.rna.tf32.f32 %0, %1;" : "=r"(u) : "f"(x));
    return __uint_as_float(u);
}

__device__ __forceinline__ int pcol(int k) {
    return (k & ~7) | ((k & 3) << 1) | ((k >> 2) & 1);
}

__device__ __forceinline__ void mma8(float* c, const uint32_t* a, const uint32_t* b) {
    asm volatile(
        "mma.sync.aligned.m16n8k8.row.col.f32.tf32.tf32.f32 "
        "{%0,%1,%2,%3},{%4,%5,%6,%7},{%8,%9},{%0,%1,%2,%3};\n"
        : "+f"(c[0]), "+f"(c[1]), "+f"(c[2]), "+f"(c[3])
        : "r"(a[0]), "r"(a[1]), "r"(a[2]), "r"(a[3]), "r"(b[0]), "r"(b[1]));
}

__device__ __forceinline__ void lda64(uint32_t* a, const float* A0, int rstride) {
    float2 x0 = *(const float2*)A0;
    float2 x1 = *(const float2*)(A0 + 8*rstride);
    a[0] = __float_as_uint(x0.x); a[1] = __float_as_uint(x1.x);
    a[2] = __float_as_uint(x0.y); a[3] = __float_as_uint(x1.y);
}

__device__ __forceinline__ void lda32(uint32_t* a, const float* A0, int rstride) {
    a[0] = __float_as_uint(A0[0]);
    a[1] = __float_as_uint(A0[8*rstride]);
    a[2] = __float_as_uint(A0[4]);
    a[3] = __float_as_uint(A0[8*rstride + 4]);
}

// register-load a row-major tile into permuted smem (stride LDP), tf32 RNA
__device__ __forceinline__ void load_perm(float* dst, const float* src, int i) {
    int row = i >> 5, c = i & 31;
    const float* g = src + row*DD + (c >> 1)*8 + (c & 1)*2;
    float2 u = *(const float2*)g;
    float2 w = *(const float2*)(g + 4);
    float4 o;
    o.x = to_tf32(u.x); o.y = to_tf32(w.x); o.z = to_tf32(u.y); o.w = to_tf32(w.y);
    *(float4*)&dst[row*LDP + c*4] = o;
}

// same + fp32 row sum-of-squares via warp reduce into g_s[row]
__device__ __forceinline__ void load_perm_g(float* dst, float* g_s, const float* src,
                                            int i, int lane) {
    int row = i >> 5, c = i & 31;
    const float* g = src + row*DD + (c >> 1)*8 + (c & 1)*2;
    float2 u = *(const float2*)g;
    float2 w = *(const float2*)(g + 4);
    float ss = u.x*u.x + u.y*u.y + w.x*w.x + w.y*w.y;
    ss += __shfl_xor_sync(0xffffffffu, ss, 16);
    ss += __shfl_xor_sync(0xffffffffu, ss, 8);
    ss += __shfl_xor_sync(0xffffffffu, ss, 4);
    ss += __shfl_xor_sync(0xffffffffu, ss, 2);
    ss += __shfl_xor_sync(0xffffffffu, ss, 1);
    if (lane == 0) g_s[row] = ss * INV2SQD;
    float4 o;
    o.x = to_tf32(u.x); o.y = to_tf32(w.x); o.z = to_tf32(u.y); o.w = to_tf32(w.y);
    *(float4*)&dst[row*LDP + c*4] = o;
}

// cp.async a ROWSx128 fp32 row-major tile into smem (stride LDV)
template<int ROWS>
__device__ __forceinline__ void cp_tilev(uint32_t sbase, const float* g, int t) {
    #pragma unroll
    for (int r = 0; r < ROWS*32/256; r++) {
        int i = t + r*256;
        uint32_t saddr = sbase + (((i >> 5)*LDV + (i & 31)*4) << 2);
        asm volatile("cp.async.cg.shared.global [%0], [%1], 16;"
                     :: "r"(saddr), "l"(g + 4*i));
    }
}

// ---------------------------------------------------------------------------
// K1: per (bh, m-tile, l-split): ctx[64m,128d] partial over 4 chunks of 128 l
// ---------------------------------------------------------------------------
__global__ __launch_bounds__(256, 1) void k1_ctx_kernel(
    const float* __restrict__ kin, const float* __restrict__ vin,
    const float* __restrict__ proj)
{
    extern __shared__ float sm[];
    float* k_s  = sm;                 // [128][136] K chunk (perm, RNA, reg-loaded)
    float* v_s  = k_s + TLK*LDP;      // [128][140] V chunk (cp.async + RNA RMW) + ones
    float* p_s  = v_s + TLK*LDV;      // [64][136]  P tile (perm, RNA, persistent)
    float* phiT = p_s + TM*LDP;       // [64 m][136] phi^T, l permuted
    float* g_s  = phiT + TM*LDP;      // [128]

    const int bx = blockIdx.x;
    const int bh = bx / (NMT*NSPL);
    const int rr = bx % (NMT*NSPL);
    const int mt = rr / NSPL;
    const int ls = rr % NSPL;
    const int t  = threadIdx.x;
    const int w  = t >> 5, lane = t & 31;
    const int gid = lane >> 2, t4 = lane & 3;

    const uint32_t vs_u = (uint32_t)__cvta_generic_to_shared(v_s);

    const float* kg = kin + (size_t)bh*LTOT*DD;
    const float* vg = vin + (size_t)bh*LTOT*DD;
    const int c0 = ls*CHK, cend = c0 + CHK;

    // prologue: V[c0] via cp.async; P via registers (RNA, permuted); ones col
    cp_tilev<TLK>(vs_u, vg + (size_t)c0*TLK*DD, t);
    asm volatile("cp.async.commit_group;");
    {
        const float* Pg = proj + (size_t)(mt*TM)*DD;
        #pragma unroll
        for (int r = 0; r < 8; r++) load_perm(p_s, Pg, t + r*256);
    }
    if (t < TLK) {   // ones column for ksum-via-MMA (v_s cols 128..135)
        *(float4*)&v_s[t*LDV + 128] = make_float4(1.f, 0.f, 0.f, 0.f);
        *(float4*)&v_s[t*LDV + 132] = make_float4(0.f, 0.f, 0.f, 0.f);
    }

    const int la = w & 3, mh2 = w >> 2;   // GEMM A: warp 32l x 32m
    const int mb2 = w & 1, db4 = w >> 1;  // GEMM B: warp 32m x 32d

    float ctxacc[2][4][4];
    #pragma unroll
    for (int ia = 0; ia < 2; ia++)
        #pragma unroll
        for (int nb = 0; nb < 4; nb++)
            #pragma unroll
            for (int i = 0; i < 4; i++) ctxacc[ia][nb][i] = 0.f;
    float ksacc[2][4];
    #pragma unroll
    for (int ia = 0; ia < 2; ia++)
        #pragma unroll
        for (int i = 0; i < 4; i++) ksacc[ia][i] = 0.f;

    for (int lc = c0; lc < cend; lc++) {
        const bool more = (lc + 1 < cend);

        // K[lc] via registers: fused fp32 g + RNA + permuted STS
        {
            const float* Kg = kg + (size_t)lc*TLK*DD;
            #pragma unroll
            for (int r = 0; r < 16; r++) load_perm_g(k_s, g_s, Kg, t + r*256, lane);
        }
        __syncthreads();   // k_s, g_s (+p_s/ones first iter) published

        // GEMM A: S[128l x 64m] = K_chunk @ P^T
        float c[2][4][4];
        #pragma unroll
        for (int ia = 0; ia < 2; ia++)
            #pragma unroll
            for (int nb = 0; nb < 4; nb++)
                #pragma unroll
                for (int i = 0; i < 4; i++) c[ia][nb][i] = 0.f;
        #pragma unroll
        for (int kk = 0; kk < DD; kk += 8) {
            uint32_t a[2][4], b[2];
            #pragma unroll
            for (int ia = 0; ia < 2; ia++)
                lda64(a[ia], k_s + (la*32 + ia*16 + gid)*LDP + kk + 2*t4, LDP);
            #pragma unroll
            for (int nb = 0; nb < 4; nb++) {
                float2 y = *(const float2*)(p_s + (mh2*32 + nb*8 + gid)*LDP + kk + 2*t4);
                b[0] = __float_as_uint(y.x); b[1] = __float_as_uint(y.y);
                mma8(c[0][nb], a[0], b);
                mma8(c[1][nb], a[1], b);
            }
        }

        // V[lc] landed (own lines) -> RNA RMW of exactly-own lines
        asm volatile("cp.async.wait_group 0;");
        #pragma unroll
        for (int r = 0; r < 16; r++) {
            int i = t + r*256;
            float* a = &v_s[(i >> 5)*LDV + (i & 31)*4];
            float4 x = *(float4*)a;
            x.x = to_tf32(x.x); x.y = to_tf32(x.y); x.z = to_tf32(x.z); x.w = to_tf32(x.w);
            *(float4*)a = x;
        }

        // exp -> phiT[m][pcol(l)]
        #pragma unroll
        for (int ia = 0; ia < 2; ia++)
            #pragma unroll
            for (int nb = 0; nb < 4; nb++) {
                int m0 = mh2*32 + nb*8 + 2*t4;
                #pragma unroll
                for (int i = 0; i < 4; i++) {
                    int l = la*32 + ia*16 + gid + ((i >> 1) << 3);
                    float ph = __expf(fmaf(c[ia][nb][i], INV_SSD, CADD - g_s[l]));
                    phiT[(m0 + (i & 1))*LDP + pcol(l)] = to_tf32(ph);
                }
            }
        __syncthreads();   // phiT + v_s published

        // GEMM B: ctx += phiT(32m x 128l) @ V(128l x 32d); db4==3 adds ones col
        #pragma unroll
        for (int kk = 0; kk < TLK; kk += 8) {
            uint32_t a[2][4];
            #pragma unroll
            for (int ia = 0; ia < 2; ia++)
                lda64(a[ia], phiT + (mb2*32 + ia*16 + gid)*LDP + kk + 2*t4, LDP);
            #pragma unroll
            for (int nb = 0; nb < 4; nb++) {
                uint32_t b[2];
                const float* B0 = v_s + (kk + t4)*LDV + db4*32 + nb*8 + gid;
                b[0] = __float_as_uint(B0[0]);
                b[1] = __float_as_uint(B0[4*LDV]);
                mma8(ctxacc[0][nb], a[0], b);
                mma8(ctxacc[1][nb], a[1], b);
            }
            if (db4 == 3) {
                uint32_t b[2];
                const float* B0 = v_s + (kk + t4)*LDV + 128 + gid;
                b[0] = __float_as_uint(B0[0]);
                b[1] = __float_as_uint(B0[4*LDV]);
                mma8(ksacc[0], a[0], b);
                mma8(ksacc[1], a[1], b);
            }
        }
        __syncthreads();   // v_s + phiT + k_s + g_s reads done

        if (more) {        // prefetch V[lc+1]; overlaps next K-load + GEMM A
            cp_tilev<TLK>(vs_u, vg + (size_t)(lc+1)*TLK*DD, t);
            asm volatile("cp.async.commit_group;");
        }
    }

    float* cg = g_ctx_part[ls] + ((size_t)bh*MM + mt*TM)*DD;
    #pragma unroll
    for (int ia = 0; ia < 2; ia++)
        #pragma unroll
        for (int nb = 0; nb < 4; nb++) {
            int m0 = mb2*32 + ia*16 + gid;
            int d  = db4*32 + nb*8 + 2*t4;
            *(float2*)&cg[m0*DD + d]       = make_float2(ctxacc[ia][nb][0], ctxacc[ia][nb][1]);
            *(float2*)&cg[(m0 + 8)*DD + d] = make_float2(ctxacc[ia][nb][2], ctxacc[ia][nb][3]);
        }
    if (db4 == 3 && t4 == 0) {
        #pragma unroll
        for (int ia = 0; ia < 2; ia++) {
            int m = mb2*32 + ia*16 + gid;
            g_ksum_part[ls][bh*MM + mt*TM + m]     = ksacc[ia][0];
            g_ksum_part[ls][bh*MM + mt*TM + m + 8] = ksacc[ia][2];
        }
    }
}

// ---------------------------------------------------------------------------
// KRED: g_ctx = sum of partials; g_ksum likewise
// ---------------------------------------------------------------------------
__global__ __launch_bounds__(256) void kred_kernel()
{
    int i = blockIdx.x*256 + threadIdx.x;
    if (i < N4CTX) {
        float4 s = ((const float4*)g_ctx_part[0])[i];
        #pragma unroll
        for (int p = 1; p < NSPL; p++) {
            float4 a = ((const float4*)g_ctx_part[p])[i];
            s.x += a.x; s.y += a.y; s.z += a.z; s.w += a.w;
        }
        ((float4*)g_ctx)[i] = s;
    } else {
        int j = i - N4CTX;
        float4 s = ((const float4*)g_ksum_part[0])[j];
        #pragma unroll
        for (int p = 1; p < NSPL; p++) {
            float4 a = ((const float4*)g_ksum_part[p])[j];
            s.x += a.x; s.y += a.y; s.z += a.z; s.w += a.w;
        }
        ((float4*)g_ksum)[j] = s;
    }
}

// ===================== K2 (unchanged — best measured 385 us) ================
__device__ __forceinline__ void cp_tile2(uint32_t sbase, const float* g, int t) {
    #pragma unroll
    for (int r = 0; r < 8; r++) {
        int i = t + r*256;
        uint32_t saddr = sbase + (((i >> 5)*LDX2 + (i & 31)*4) << 2);
        asm volatile("cp.async.cg.shared.global [%0], [%1], 16;"
                     :: "r"(saddr), "l"(g + 4*i));
    }
}

__global__ __launch_bounds__(256, 1) void k2_out_kernel(
    const float* __restrict__ qin, const float* __restrict__ proj,
    float* __restrict__ out)
{
    extern __shared__ float sm[];
    float* q_s   = sm;
    float* p_buf = q_s + TL2*LDX2;
    float* c_buf = p_buf + TM*LDX2;
    float* phi_s = c_buf + TM*LDX2;
    float* g_s   = phi_s + TL2*PT2;
    float* dinv  = g_s + TL2;

    const int bh = blockIdx.x / NLT2;
    const int lt = blockIdx.x % NLT2;
    const int t  = threadIdx.x;
    const int w  = t >> 5, lane = t & 31;
    const int gid = lane >> 2, t4 = lane & 3;

    const uint32_t pb_u = (uint32_t)__cvta_generic_to_shared(p_buf);
    const uint32_t cb_u = (uint32_t)__cvta_generic_to_shared(c_buf);

    cp_tile2(pb_u, proj, t);
    asm volatile("cp.async.commit_group;");

    {
        const float4* Qg = (const float4*)(qin + ((size_t)bh*LTOT + lt*TL2)*DD);
        #pragma unroll
        for (int r = 0; r < 16; r++) {
            int i = t + r*256;
            float4 v = Qg[i];
            float ss = v.x*v.x + v.y*v.y + v.z*v.z + v.w*v.w;
            ss += __shfl_xor_sync(0xffffffffu, ss, 16);
            ss += __shfl_xor_sync(0xffffffffu, ss, 8);
            ss += __shfl_xor_sync(0xffffffffu, ss, 4);
            ss += __shfl_xor_sync(0xffffffffu, ss, 2);
            ss += __shfl_xor_sync(0xffffffffu, ss, 1);
            if (lane == 0) g_s[r*8 + w] = ss * INV2SQD;
            v.x = to_tf32(v.x); v.y = to_tf32(v.y); v.z = to_tf32(v.z); v.w = to_tf32(v.w);
            *(float4*)&q_s[(i>>5)*LDX2 + (i&31)*4] = v;
        }
    }

    const int lb = w & 3;
    const int mh = w >> 2;
    const int db = w >> 2;

    float oacc[2][8][4];
    #pragma unroll
    for (int ia = 0; ia < 2; ia++)
        #pragma unroll
        for (int nb = 0; nb < 8; nb++)
            #pragma unroll
            for (int i = 0; i < 4; i++) oacc[ia][nb][i] = 0.f;
    float dks[2][4];
    #pragma unroll
    for (int ia = 0; ia < 2; ia++)
        #pragma unroll
        for (int i = 0; i < 4; i++) dks[ia][i] = 0.f;

    for (int mc = 0; mc < NMT; mc++) {
        __syncthreads();
        cp_tile2(cb_u, g_ctx + ((size_t)bh*MM + mc*TM)*DD, t);
        asm volatile("cp.async.commit_group;");
        asm volatile("cp.async.wait_group 1;");
        __syncthreads();

        float c[2][4][4];
        #pragma unroll
        for (int ia = 0; ia < 2; ia++)
            #pragma unroll
            for (int nb = 0; nb < 4; nb++)
                #pragma unroll
                for (int i = 0; i < 4; i++) c[ia][nb][i] = 0.f;
        #pragma unroll
        for (int kk = 0; kk < DD; kk += 8) {
            uint32_t a[2][4], b[2];
            #pragma unroll
            for (int ia = 0; ia < 2; ia++)
                lda32(a[ia], q_s + (lb*32 + ia*16 + gid)*LDX2 + kk + t4, LDX2);
            #pragma unroll
            for (int nb = 0; nb < 4; nb++) {
                const float* B0 = p_buf + (mh*32 + nb*8 + gid)*LDX2 + kk + t4;
                b[0] = __float_as_uint(B0[0]);
                b[1] = __float_as_uint(B0[4]);
                mma8(c[0][nb], a[0], b);
                mma8(c[1][nb], a[1], b);
            }
        }
        __syncthreads();

        if (mc + 1 < NMT) cp_tile2(pb_u, proj + (size_t)((mc+1)*TM)*DD, t);
        asm volatile("cp.async.commit_group;");

        #pragma unroll
        for (int ia = 0; ia < 2; ia++)
            #pragma unroll
            for (int nb = 0; nb < 4; nb++) {
                int m0 = mh*32 + nb*8 + 2*t4;
                #pragma unroll
                for (int i = 0; i < 4; i++) {
                    int l = lb*32 + ia*16 + gid + ((i >> 1) << 3);
                    float ph = __expf(fmaf(c[ia][nb][i], INV_SSD, CADD - g_s[l]));
                    phi_s[l*PT2 + m0 + (i & 1)] = to_tf32(ph);
                }
            }
        if (t < TM) {
            float ks = to_tf32(g_ksum[bh*MM + mc*TM + t]);
            *(float4*)&c_buf[t*LDX2 + 128] = make_float4(ks, 0.f, 0.f, 0.f);
            *(float4*)&c_buf[t*LDX2 + 132] = make_float4(0.f, 0.f, 0.f, 0.f);
        }
        asm volatile("cp.async.wait_group 1;");
        __syncthreads();

        #pragma unroll
        for (int kk = 0; kk < TM; kk += 8) {
            uint32_t a[2][4];
            #pragma unroll
            for (int ia = 0; ia < 2; ia++)
                lda32(a[ia], phi_s + (lb*32 + ia*16 + gid)*PT2 + kk + t4, PT2);
            #pragma unroll
            for (int nb = 0; nb < 8; nb++) {
                uint32_t b[2];
                const float* B0 = c_buf + (kk + t4)*LDX2 + db*64 + nb*8 + gid;
                b[0] = __float_as_uint(B0[0]);
                b[1] = __float_as_uint(B0[4*LDX2]);
                mma8(oacc[0][nb], a[0], b);
                mma8(oacc[1][nb], a[1], b);
            }
            if (db == 1) {
                uint32_t b[2];
                const float* B0 = c_buf + (kk + t4)*LDX2 + 128 + gid;
                b[0] = __float_as_uint(B0[0]);
                b[1] = __float_as_uint(B0[4*LDX2]);
                mma8(dks[0], a[0], b);
                mma8(dks[1], a[1], b);
            }
        }
    }

    if (db == 1 && t4 == 0) {
        #pragma unroll
        for (int ia = 0; ia < 2; ia++) {
            int l = lb*32 + ia*16 + gid;
            dinv[l]     = 1.0f / dks[ia][0];
            dinv[l + 8] = 1.0f / dks[ia][2];
        }
    }
    __syncthreads();

    float* og = out + ((size_t)bh*LTOT + lt*TL2)*DD;
    #pragma unroll
    for (int ia = 0; ia < 2; ia++)
        #pragma unroll
        for (int nb = 0; nb < 8; nb++) {
            int l0 = lb*32 + ia*16 + gid;
            int d  = db*64 + nb*8 + 2*t4;
            float i0 = dinv[l0], i1 = dinv[l0 + 8];
            *(float2*)&og[l0*DD + d]       = make_float2(oacc[ia][nb][0]*i0, oacc[ia][nb][1]*i0);
            *(float2*)&og[(l0 + 8)*DD + d] = make_float2(oacc[ia][nb][2]*i1, oacc[ia][nb][3]*i1);
        }
}

extern "C" void kernel_launch(void* const* d_in, const int* in_sizes, int n_in,
                              void* d_out, int out_size) {
    const float* q    = (const float*)d_in[0];
    const float* k    = (const float*)d_in[1];
    const float* v    = (const float*)d_in[2];
    const float* proj = (const float*)d_in[3];
    float* out = (float*)d_out;

    size_t smem1 = (TLK*LDP + TLK*LDV + TM*LDP + TM*LDP + TLK) * sizeof(float);  // ~211.5 KB
    size_t smem2 = (TL2*LDX2 + 2*TM*LDX2 + TL2*PT2 + TL2 + TL2) * sizeof(float); // ~179 KB
    cudaFuncSetAttribute(k1_ctx_kernel, cudaFuncAttributeMaxDynamicSharedMemorySize, (int)smem1);
    cudaFuncSetAttribute(k2_out_kernel, cudaFuncAttributeMaxDynamicSharedMemorySize, (int)smem2);

    k1_ctx_kernel<<<BH * NMT * NSPL, 256, smem1>>>(k, v, proj);
    kred_kernel<<<(N4CTX + N4KS) / 256, 256>>>();
    k2_out_kernel<<<BH * NLT2, 256, smem2>>>(q, proj, out);
}

// round 11
// speedup vs baseline: 1.1413x; 1.1413x over previous
#include <cuda_runtime.h>
#include <cstdint>

#define BH   32
#define LTOT 4096
#define DD   128
#define MM   640
#define TL   64
#define TM   64
#define NMT  (MM/TM)    // 10
#define NLT  (LTOT/TL)  // 64
#define NSPL 8          // k1 L-split
#define CHK  (NLT/NSPL) // 8 chunks per k1 block
#define TL2  128
#define NLT2 (LTOT/TL2) // 32
#define LDX1 136        // k1 strides (permuted layout)
#define PT1  72
#define LDX2 140        // k2 strides (plain layout)
#define PT2  68

#define N4CTX (BH*MM*DD/4)  // 655360
#define N4KS  (BH*MM/4)     // 5120

#define INV_SSD  0.2973017787506803f
#define INV2SQD  0.04419417382415922f
#define CADD    -3.2306341575510305f

__device__ float g_ctx[(size_t)BH * MM * DD];
__device__ float g_ksum[BH * MM];
__device__ float g_ctx_part[NSPL][(size_t)BH * MM * DD];   // 84 MB
__device__ float g_ksum_part[NSPL][BH * MM];

__device__ __forceinline__ float to_tf32(float x) {
    uint32_t u;
    asm("cvt.rna.tf32.f32 %0, %1;" : "=r"(u) : "f"(x));
    return __uint_as_float(u);
}

__device__ __forceinline__ int pcol(int k) {
    return (k & ~7) | ((k & 3) << 1) | ((k >> 2) & 1);
}

__device__ __forceinline__ void mma8(float* c, const uint32_t* a, const uint32_t* b) {
    asm volatile(
        "mma.sync.aligned.m16n8k8.row.col.f32.tf32.tf32.f32 "
        "{%0,%1,%2,%3},{%4,%5,%6,%7},{%8,%9},{%0,%1,%2,%3};\n"
        : "+f"(c[0]), "+f"(c[1]), "+f"(c[2]), "+f"(c[3])
        : "r"(a[0]), "r"(a[1]), "r"(a[2]), "r"(a[3]), "r"(b[0]), "r"(b[1]));
}

// ===================== K1 helpers (permuted layout, stride LDX1) ============
__device__ __forceinline__ void load_perm(float* dst, const float* src, int i) {
    int row = i >> 5, c = i & 31;
    const float* g = src + row*DD + (c >> 1)*8 + (c & 1)*2;
    float2 u = *(const float2*)g;
    float2 w = *(const float2*)(g + 4);
    float4 o;
    o.x = to_tf32(u.x); o.y = to_tf32(w.x); o.z = to_tf32(u.y); o.w = to_tf32(w.y);
    *(float4*)&dst[row*LDX1 + c*4] = o;
}

__device__ __forceinline__ void load_perm_g(float* dst, float* g_s, const float* src,
                                            int i, int lane) {
    int row = i >> 5, c = i & 31;
    const float* g = src + row*DD + (c >> 1)*8 + (c & 1)*2;
    float2 u = *(const float2*)g;
    float2 w = *(const float2*)(g + 4);
    float ss = u.x*u.x + u.y*u.y + w.x*w.x + w.y*w.y;
    ss += __shfl_xor_sync(0xffffffffu, ss, 16);
    ss += __shfl_xor_sync(0xffffffffu, ss, 8);
    ss += __shfl_xor_sync(0xffffffffu, ss, 4);
    ss += __shfl_xor_sync(0xffffffffu, ss, 2);
    ss += __shfl_xor_sync(0xffffffffu, ss, 1);
    if (lane == 0) g_s[row] = ss * INV2SQD;
    float4 o;
    o.x = to_tf32(u.x); o.y = to_tf32(w.x); o.z = to_tf32(u.y); o.w = to_tf32(w.y);
    *(float4*)&dst[row*LDX1 + c*4] = o;
}

__device__ __forceinline__ void load_plain1(float* dst, const float4* src, int i) {
    float4 v = src[i];
    v.x = to_tf32(v.x); v.y = to_tf32(v.y); v.z = to_tf32(v.z); v.w = to_tf32(v.w);
    *(float4*)&dst[(i >> 5)*LDX1 + (i & 31)*4] = v;
}

__device__ __forceinline__ void lda64(uint32_t* a, const float* A0, int rstride) {
    float2 x0 = *(const float2*)A0;
    float2 x1 = *(const float2*)(A0 + 8*rstride);
    a[0] = __float_as_uint(x0.x); a[1] = __float_as_uint(x1.x);
    a[2] = __float_as_uint(x0.y); a[3] = __float_as_uint(x1.y);
}

__device__ __forceinline__ void lda32(uint32_t* a, const float* A0, int rstride) {
    a[0] = __float_as_uint(A0[0]);
    a[1] = __float_as_uint(A0[8*rstride]);
    a[2] = __float_as_uint(A0[4]);
    a[3] = __float_as_uint(A0[8*rstride + 4]);
}

// ---------------------------------------------------------------------------
// K1 (R7-exact): per (bh, m-tile, l-split): partial ctx over 8 chunks of 64 l
// ---------------------------------------------------------------------------
__global__ __launch_bounds__(256, 2) void k1_ctx_kernel(
    const float* __restrict__ kin, const float* __restrict__ vin,
    const float* __restrict__ proj)
{
    extern __shared__ float sm[];
    float* kv_s = sm;                // [64][136]
    float* p_s  = kv_s + TL*LDX1;    // [64][136]
    float* phiT = p_s  + TM*LDX1;    // [64 m][72]
    float* g_s  = phiT + TM*PT1;     // [64]

    const int bx = blockIdx.x;
    const int bh = bx / (NMT*NSPL);
    const int rr = bx % (NMT*NSPL);
    const int mt = rr / NSPL;
    const int ls = rr % NSPL;
    const int t  = threadIdx.x;
    const int w  = t >> 5, lane = t & 31;
    const int gid = lane >> 2, t4 = lane & 3;

    {
        const float* Pg = proj + (size_t)(mt*TM)*DD;
        #pragma unroll
        for (int r = 0; r < 8; r++) load_perm(p_s, Pg, t + r*256);
    }
    if (t < TL) {
        *(float4*)&kv_s[t*LDX1 + 128] = make_float4(1.f, 0.f, 0.f, 0.f);
        *(float4*)&kv_s[t*LDX1 + 132] = make_float4(0.f, 0.f, 0.f, 0.f);
    }

    const float* kg = kin + (size_t)bh*LTOT*DD;
    const float* vg = vin + (size_t)bh*LTOT*DD;

    const int lb = w & 3, mh = w >> 2;
    const int mb = w & 3, db = w >> 2;

    float ctxacc[8][4];
    #pragma unroll
    for (int nb = 0; nb < 8; nb++)
        #pragma unroll
        for (int i = 0; i < 4; i++) ctxacc[nb][i] = 0.f;
    float ksacc[4] = {0.f, 0.f, 0.f, 0.f};

    for (int lc = ls*CHK; lc < ls*CHK + CHK; lc++) {
        __syncthreads();
        {
            const float* Kg = kg + (size_t)lc*TL*DD;
            #pragma unroll
            for (int r = 0; r < 8; r++) load_perm_g(kv_s, g_s, Kg, t + r*256, lane);
        }
        __syncthreads();

        float c[4][4];
        #pragma unroll
        for (int nb = 0; nb < 4; nb++)
            #pragma unroll
            for (int i = 0; i < 4; i++) c[nb][i] = 0.f;
        #pragma unroll
        for (int kk = 0; kk < DD; kk += 8) {
            uint32_t a[4], b[2];
            lda64(a, kv_s + (lb*16 + gid)*LDX1 + kk + 2*t4, LDX1);
            #pragma unroll
            for (int nb = 0; nb < 4; nb++) {
                float2 y = *(const float2*)(p_s + (mh*32 + nb*8 + gid)*LDX1 + kk + 2*t4);
                b[0] = __float_as_uint(y.x); b[1] = __float_as_uint(y.y);
                mma8(c[nb], a, b);
            }
        }
        __syncthreads();

        #pragma unroll
        for (int nb = 0; nb < 4; nb++) {
            int m0 = mh*32 + nb*8 + 2*t4;
            #pragma unroll
            for (int i = 0; i < 4; i++) {
                int l = lb*16 + gid + ((i >> 1) << 3);
                float ph = __expf(fmaf(c[nb][i], INV_SSD, CADD - g_s[l]));
                phiT[(m0 + (i & 1))*PT1 + pcol(l)] = to_tf32(ph);
            }
        }
        {
            const float4* Vg = (const float4*)(vg + (size_t)lc*TL*DD);
            #pragma unroll
            for (int r = 0; r < 8; r++) load_plain1(kv_s, Vg, t + r*256);
        }
        __syncthreads();

        #pragma unroll
        for (int kk = 0; kk < TL; kk += 8) {
            uint32_t a[4];
            lda64(a, phiT + (mb*16 + gid)*PT1 + kk + 2*t4, PT1);
            #pragma unroll
            for (int nb = 0; nb < 8; nb++) {
                uint32_t b[2];
                const float* B0 = kv_s + (kk + t4)*LDX1 + db*64 + nb*8 + gid;
                b[0] = __float_as_uint(B0[0]);
                b[1] = __float_as_uint(B0[4*LDX1]);
                mma8(ctxacc[nb], a, b);
            }
            if (db == 1) {
                uint32_t b[2];
                const float* B0 = kv_s + (kk + t4)*LDX1 + 128 + gid;
                b[0] = __float_as_uint(B0[0]);
                b[1] = __float_as_uint(B0[4*LDX1]);
                mma8(ksacc, a, b);
            }
        }
    }

    float* cg = g_ctx_part[ls] + ((size_t)bh*MM + mt*TM)*DD;
    #pragma unroll
    for (int nb = 0; nb < 8; nb++) {
        int m0 = mb*16 + gid;
        int d  = db*64 + nb*8 + 2*t4;
        *(float2*)&cg[m0*DD + d]       = make_float2(ctxacc[nb][0], ctxacc[nb][1]);
        *(float2*)&cg[(m0 + 8)*DD + d] = make_float2(ctxacc[nb][2], ctxacc[nb][3]);
    }
    if (db == 1 && t4 == 0) {
        g_ksum_part[ls][bh*MM + mt*TM + mb*16 + gid]     = ksacc[0];
        g_ksum_part[ls][bh*MM + mt*TM + mb*16 + gid + 8] = ksacc[2];
    }
}

// ---------------------------------------------------------------------------
// KRED: g_ctx = sum of 8 partials; g_ksum likewise
// ---------------------------------------------------------------------------
__global__ __launch_bounds__(256) void kred_kernel()
{
    int i = blockIdx.x*256 + threadIdx.x;
    if (i < N4CTX) {
        float4 s = ((const float4*)g_ctx_part[0])[i];
        #pragma unroll
        for (int p = 1; p < NSPL; p++) {
            float4 a = ((const float4*)g_ctx_part[p])[i];
            s.x += a.x; s.y += a.y; s.z += a.z; s.w += a.w;
        }
        ((float4*)g_ctx)[i] = s;
    } else {
        int j = i - N4CTX;
        float4 s = ((const float4*)g_ksum_part[0])[j];
        #pragma unroll
        for (int p = 1; p < NSPL; p++) {
            float4 a = ((const float4*)g_ksum_part[p])[j];
            s.x += a.x; s.y += a.y; s.z += a.z; s.w += a.w;
        }
        ((float4*)g_ksum)[j] = s;
    }
}

// ===================== K2: 512 threads, 16 warps, same 128lx128d tile =======
__device__ __forceinline__ void cp_tile2(uint32_t sbase, const float* g, int t) {
    #pragma unroll
    for (int r = 0; r < 4; r++) {          // 512 threads x 4 = 2048 float4 = 64x128
        int i = t + r*512;
        uint32_t saddr = sbase + (((i >> 5)*LDX2 + (i & 31)*4) << 2);
        asm volatile("cp.async.cg.shared.global [%0], [%1], 16;"
                     :: "r"(saddr), "l"(g + 4*i));
    }
}

__global__ __launch_bounds__(512, 1) void k2_out_kernel(
    const float* __restrict__ qin, const float* __restrict__ proj,
    float* __restrict__ out)
{
    extern __shared__ float sm[];
    float* q_s   = sm;                  // [128][140]  Q (RNA tf32, persistent)
    float* p_buf = q_s + TL2*LDX2;      // [64][140]   P chunk (cp.async)
    float* c_buf = p_buf + TM*LDX2;     // [64][140]   ctx chunk (cp.async) + ks col
    float* phi_s = c_buf + TM*LDX2;     // [128 l][68 m]
    float* g_s   = phi_s + TL2*PT2;     // [128]
    float* dinv  = g_s + TL2;           // [128]

    const int bh = blockIdx.x / NLT2;
    const int lt = blockIdx.x % NLT2;
    const int t  = threadIdx.x;
    const int w  = t >> 5, lane = t & 31;
    const int gid = lane >> 2, t4 = lane & 3;

    const uint32_t pb_u = (uint32_t)__cvta_generic_to_shared(p_buf);
    const uint32_t cb_u = (uint32_t)__cvta_generic_to_shared(c_buf);

    cp_tile2(pb_u, proj, t);
    asm volatile("cp.async.commit_group;");

    // Q tile 128x128 + g (fp32 via warp reduce during load): row = w + 16r
    {
        const float4* Qg = (const float4*)(qin + ((size_t)bh*LTOT + lt*TL2)*DD);
        #pragma unroll
        for (int r = 0; r < 8; r++) {
            int i = t + r*512;
            float4 v = Qg[i];
            float ss = v.x*v.x + v.y*v.y + v.z*v.z + v.w*v.w;
            ss += __shfl_xor_sync(0xffffffffu, ss, 16);
            ss += __shfl_xor_sync(0xffffffffu, ss, 8);
            ss += __shfl_xor_sync(0xffffffffu, ss, 4);
            ss += __shfl_xor_sync(0xffffffffu, ss, 2);
            ss += __shfl_xor_sync(0xffffffffu, ss, 1);
            if (lane == 0) g_s[i >> 5] = ss * INV2SQD;
            v.x = to_tf32(v.x); v.y = to_tf32(v.y); v.z = to_tf32(v.z); v.w = to_tf32(v.w);
            *(float4*)&q_s[(i>>5)*LDX2 + (i&31)*4] = v;
        }
    }

    const int la = w & 7;     // l-block of 16 (both GEMMs)
    const int mh = w >> 3;    // GEMM A: m-half of 32
    const int db = w >> 3;    // GEMM B: d-half of 64

    float oacc[8][4];
    #pragma unroll
    for (int nb = 0; nb < 8; nb++)
        #pragma unroll
        for (int i = 0; i < 4; i++) oacc[nb][i] = 0.f;
    float dks[4] = {0.f, 0.f, 0.f, 0.f};

    for (int mc = 0; mc < NMT; mc++) {
        __syncthreads();   // prev GEMM B done -> c_buf/phi free; q/g visible (1st iter)
        cp_tile2(cb_u, g_ctx + ((size_t)bh*MM + mc*TM)*DD, t);
        asm volatile("cp.async.commit_group;");        // group C[mc]
        asm volatile("cp.async.wait_group 1;");        // P[mc] arrived
        __syncthreads();                               // p_buf published

        // GEMM A: S[128l x 64m] = Q @ P_chunk^T ; warp tile 16l x 32m
        float c[4][4];
        #pragma unroll
        for (int nb = 0; nb < 4; nb++)
            #pragma unroll
            for (int i = 0; i < 4; i++) c[nb][i] = 0.f;
        #pragma unroll
        for (int kk = 0; kk < DD; kk += 8) {
            uint32_t a[4], b[2];
            lda32(a, q_s + (la*16 + gid)*LDX2 + kk + t4, LDX2);
            #pragma unroll
            for (int nb = 0; nb < 4; nb++) {
                const float* B0 = p_buf + (mh*32 + nb*8 + gid)*LDX2 + kk + t4;
                b[0] = __float_as_uint(B0[0]);
                b[1] = __float_as_uint(B0[4]);
                mma8(c[nb], a, b);
            }
        }
        __syncthreads();   // p_buf reads done

        if (mc + 1 < NMT) cp_tile2(pb_u, proj + (size_t)((mc+1)*TM)*DD, t);
        asm volatile("cp.async.commit_group;");        // group P[mc+1]

        // exp -> phi_s[l][m]
        #pragma unroll
        for (int nb = 0; nb < 4; nb++) {
            int m0 = mh*32 + nb*8 + 2*t4;
            #pragma unroll
            for (int i = 0; i < 4; i++) {
                int l = la*16 + gid + ((i >> 1) << 3);
                float ph = __expf(fmaf(c[nb][i], INV_SSD, CADD - g_s[l]));
                phi_s[l*PT2 + m0 + (i & 1)] = to_tf32(ph);
            }
        }
        if (t < TM) {
            float ks = to_tf32(g_ksum[bh*MM + mc*TM + t]);
            *(float4*)&c_buf[t*LDX2 + 128] = make_float4(ks, 0.f, 0.f, 0.f);
            *(float4*)&c_buf[t*LDX2 + 132] = make_float4(0.f, 0.f, 0.f, 0.f);
        }
        asm volatile("cp.async.wait_group 1;");        // C[mc] arrived
        __syncthreads();                               // c_buf + phi + ks published

        // GEMM B: out[16l x 64d] += phi(16l x 64m) @ ctx(64m x 64d); db==1 adds ks col
        #pragma unroll
        for (int kk = 0; kk < TM; kk += 8) {
            uint32_t a[4];
            lda32(a, phi_s + (la*16 + gid)*PT2 + kk + t4, PT2);
            #pragma unroll
            for (int nb = 0; nb < 8; nb++) {
                uint32_t b[2];
                const float* B0 = c_buf + (kk + t4)*LDX2 + db*64 + nb*8 + gid;
                b[0] = __float_as_uint(B0[0]);
                b[1] = __float_as_uint(B0[4*LDX2]);
                mma8(oacc[nb], a, b);
            }
            if (db == 1) {
                uint32_t b[2];
                const float* B0 = c_buf + (kk + t4)*LDX2 + 128 + gid;
                b[0] = __float_as_uint(B0[0]);
                b[1] = __float_as_uint(B0[4*LDX2]);
                mma8(dks, a, b);
            }
        }
    }

    // denominator: db==1 warps (la = 0..7 covers all 128 l), t4==0 lanes
    if (db == 1 && t4 == 0) {
        int l = la*16 + gid;
        dinv[l]     = 1.0f / dks[0];
        dinv[l + 8] = 1.0f / dks[2];
    }
    __syncthreads();

    float* og = out + ((size_t)bh*LTOT + lt*TL2)*DD;
    #pragma unroll
    for (int nb = 0; nb < 8; nb++) {
        int l0 = la*16 + gid;
        int d  = db*64 + nb*8 + 2*t4;
        float i0 = dinv[l0], i1 = dinv[l0 + 8];
        *(float2*)&og[l0*DD + d]       = make_float2(oacc[nb][0]*i0, oacc[nb][1]*i0);
        *(float2*)&og[(l0 + 8)*DD + d] = make_float2(oacc[nb][2]*i1, oacc[nb][3]*i1);
    }
}

extern "C" void kernel_launch(void* const* d_in, const int* in_sizes, int n_in,
                              void* d_out, int out_size) {
    const float* q    = (const float*)d_in[0];
    const float* k    = (const float*)d_in[1];
    const float* v    = (const float*)d_in[2];
    const float* proj = (const float*)d_in[3];
    float* out = (float*)d_out;

    size_t smem1 = (TL*LDX1 + TM*LDX1 + TM*PT1 + 64) * sizeof(float);              // ~86.3 KB
    size_t smem2 = (TL2*LDX2 + 2*TM*LDX2 + TL2*PT2 + TL2 + TL2) * sizeof(float);   // ~179 KB
    cudaFuncSetAttribute(k1_ctx_kernel, cudaFuncAttributeMaxDynamicSharedMemorySize, (int)smem1);
    cudaFuncSetAttribute(k2_out_kernel, cudaFuncAttributeMaxDynamicSharedMemorySize, (int)smem2);

    k1_ctx_kernel<<<BH * NMT * NSPL, 256, smem1>>>(k, v, proj);
    kred_kernel<<<(N4CTX + N4KS) / 256, 256>>>();
    k2_out_kernel<<<BH * NLT2, 512, smem2>>>(q, proj, out);
}

// round 13
// speedup vs baseline: 1.1755x; 1.0300x over previous
#include <cuda_runtime.h>
#include <cstdint>

#define BH   32
#define LTOT 4096
#define DD   128
#define MM   640
#define TL   64
#define TM   64
#define NMT  (MM/TM)    // 10
#define NLT  (LTOT/TL)  // 64
#define NSPL 8          // k1 L-split
#define CHK  (NLT/NSPL) // 8 chunks per k1 block
#define TL2  128
#define NLT2 (LTOT/TL2) // 32
#define LDX1 136        // permuted-layout stride (k1 tiles + k2 Q): 136 mod 32 == 8
#define PT1  72
#define LDX2 140        // k2 plain strides (P/ctx)
#define PT2  68

#define N4CTX (BH*MM*DD/4)  // 655360
#define N4KS  (BH*MM/4)     // 5120

#define INV_SSD  0.2973017787506803f
#define INV2SQD  0.04419417382415922f
#define CADD    -3.2306341575510305f

__device__ float g_ctx[(size_t)BH * MM * DD];
__device__ float g_ksum[BH * MM];
__device__ float g_ctx_part[NSPL][(size_t)BH * MM * DD];   // 84 MB
__device__ float g_ksum_part[NSPL][BH * MM];

__device__ __forceinline__ float to_tf32(float x) {
    uint32_t u;
    asm("cvt.rna.tf32.f32 %0, %1;" : "=r"(u) : "f"(x));
    return __uint_as_float(u);
}

__device__ __forceinline__ int pcol(int k) {
    return (k & ~7) | ((k & 3) << 1) | ((k >> 2) & 1);
}

__device__ __forceinline__ void mma8(float* c, const uint32_t* a, const uint32_t* b) {
    asm volatile(
        "mma.sync.aligned.m16n8k8.row.col.f32.tf32.tf32.f32 "
        "{%0,%1,%2,%3},{%4,%5,%6,%7},{%8,%9},{%0,%1,%2,%3};\n"
        : "+f"(c[0]), "+f"(c[1]), "+f"(c[2]), "+f"(c[3])
        : "r"(a[0]), "r"(a[1]), "r"(a[2]), "r"(a[3]), "r"(b[0]), "r"(b[1]));
}

// ============ permuted-layout helpers (stride LDX1) =========================
__device__ __forceinline__ void load_perm(float* dst, const float* src, int i) {
    int row = i >> 5, c = i & 31;
    const float* g = src + row*DD + (c >> 1)*8 + (c & 1)*2;
    float2 u = *(const float2*)g;
    float2 w = *(const float2*)(g + 4);
    float4 o;
    o.x = to_tf32(u.x); o.y = to_tf32(w.x); o.z = to_tf32(u.y); o.w = to_tf32(w.y);
    *(float4*)&dst[row*LDX1 + c*4] = o;
}

__device__ __forceinline__ void load_perm_g(float* dst, float* g_s, const float* src,
                                            int i, int lane) {
    int row = i >> 5, c = i & 31;
    const float* g = src + row*DD + (c >> 1)*8 + (c & 1)*2;
    float2 u = *(const float2*)g;
    float2 w = *(const float2*)(g + 4);
    float ss = u.x*u.x + u.y*u.y + w.x*w.x + w.y*w.y;
    ss += __shfl_xor_sync(0xffffffffu, ss, 16);
    ss += __shfl_xor_sync(0xffffffffu, ss, 8);
    ss += __shfl_xor_sync(0xffffffffu, ss, 4);
    ss += __shfl_xor_sync(0xffffffffu, ss, 2);
    ss += __shfl_xor_sync(0xffffffffu, ss, 1);
    if (lane == 0) g_s[row] = ss * INV2SQD;
    float4 o;
    o.x = to_tf32(u.x); o.y = to_tf32(w.x); o.z = to_tf32(u.y); o.w = to_tf32(w.y);
    *(float4*)&dst[row*LDX1 + c*4] = o;
}

__device__ __forceinline__ void load_plain1(float* dst, const float4* src, int i) {
    float4 v = src[i];
    v.x = to_tf32(v.x); v.y = to_tf32(v.y); v.z = to_tf32(v.z); v.w = to_tf32(v.w);
    *(float4*)&dst[(i >> 5)*LDX1 + (i & 31)*4] = v;
}

__device__ __forceinline__ void lda64(uint32_t* a, const float* A0, int rstride) {
    float2 x0 = *(const float2*)A0;
    float2 x1 = *(const float2*)(A0 + 8*rstride);
    a[0] = __float_as_uint(x0.x); a[1] = __float_as_uint(x1.x);
    a[2] = __float_as_uint(x0.y); a[3] = __float_as_uint(x1.y);
}

__device__ __forceinline__ void lda32(uint32_t* a, const float* A0, int rstride) {
    a[0] = __float_as_uint(A0[0]);
    a[1] = __float_as_uint(A0[8*rstride]);
    a[2] = __float_as_uint(A0[4]);
    a[3] = __float_as_uint(A0[8*rstride + 4]);
}

// ---------------------------------------------------------------------------
// K1 (R7-exact, measured 454us): per (bh, m-tile, l-split), 8 chunks of 64 l
// ---------------------------------------------------------------------------
__global__ __launch_bounds__(256, 2) void k1_ctx_kernel(
    const float* __restrict__ kin, const float* __restrict__ vin,
    const float* __restrict__ proj)
{
    extern __shared__ float sm[];
    float* kv_s = sm;                // [64][136]
    float* p_s  = kv_s + TL*LDX1;    // [64][136]
    float* phiT = p_s  + TM*LDX1;    // [64 m][72]
    float* g_s  = phiT + TM*PT1;     // [64]

    const int bx = blockIdx.x;
    const int bh = bx / (NMT*NSPL);
    const int rr = bx % (NMT*NSPL);
    const int mt = rr / NSPL;
    const int ls = rr % NSPL;
    const int t  = threadIdx.x;
    const int w  = t >> 5, lane = t & 31;
    const int gid = lane >> 2, t4 = lane & 3;

    {
        const float* Pg = proj + (size_t)(mt*TM)*DD;
        #pragma unroll
        for (int r = 0; r < 8; r++) load_perm(p_s, Pg, t + r*256);
    }
    if (t < TL) {
        *(float4*)&kv_s[t*LDX1 + 128] = make_float4(1.f, 0.f, 0.f, 0.f);
        *(float4*)&kv_s[t*LDX1 + 132] = make_float4(0.f, 0.f, 0.f, 0.f);
    }

    const float* kg = kin + (size_t)bh*LTOT*DD;
    const float* vg = vin + (size_t)bh*LTOT*DD;

    const int lb = w & 3, mh = w >> 2;
    const int mb = w & 3, db = w >> 2;

    float ctxacc[8][4];
    #pragma unroll
    for (int nb = 0; nb < 8; nb++)
        #pragma unroll
        for (int i = 0; i < 4; i++) ctxacc[nb][i] = 0.f;
    float ksacc[4] = {0.f, 0.f, 0.f, 0.f};

    for (int lc = ls*CHK; lc < ls*CHK + CHK; lc++) {
        __syncthreads();
        {
            const float* Kg = kg + (size_t)lc*TL*DD;
            #pragma unroll
            for (int r = 0; r < 8; r++) load_perm_g(kv_s, g_s, Kg, t + r*256, lane);
        }
        __syncthreads();

        float c[4][4];
        #pragma unroll
        for (int nb = 0; nb < 4; nb++)
            #pragma unroll
            for (int i = 0; i < 4; i++) c[nb][i] = 0.f;
        #pragma unroll
        for (int kk = 0; kk < DD; kk += 8) {
            uint32_t a[4], b[2];
            lda64(a, kv_s + (lb*16 + gid)*LDX1 + kk + 2*t4, LDX1);
            #pragma unroll
            for (int nb = 0; nb < 4; nb++) {
                float2 y = *(const float2*)(p_s + (mh*32 + nb*8 + gid)*LDX1 + kk + 2*t4);
                b[0] = __float_as_uint(y.x); b[1] = __float_as_uint(y.y);
                mma8(c[nb], a, b);
            }
        }
        __syncthreads();

        #pragma unroll
        for (int nb = 0; nb < 4; nb++) {
            int m0 = mh*32 + nb*8 + 2*t4;
            #pragma unroll
            for (int i = 0; i < 4; i++) {
                int l = lb*16 + gid + ((i >> 1) << 3);
                float ph = __expf(fmaf(c[nb][i], INV_SSD, CADD - g_s[l]));
                phiT[(m0 + (i & 1))*PT1 + pcol(l)] = to_tf32(ph);
            }
        }
        {
            const float4* Vg = (const float4*)(vg + (size_t)lc*TL*DD);
            #pragma unroll
            for (int r = 0; r < 8; r++) load_plain1(kv_s, Vg, t + r*256);
        }
        __syncthreads();

        #pragma unroll
        for (int kk = 0; kk < TL; kk += 8) {
            uint32_t a[4];
            lda64(a, phiT + (mb*16 + gid)*PT1 + kk + 2*t4, PT1);
            #pragma unroll
            for (int nb = 0; nb < 8; nb++) {
                uint32_t b[2];
                const float* B0 = kv_s + (kk + t4)*LDX1 + db*64 + nb*8 + gid;
                b[0] = __float_as_uint(B0[0]);
                b[1] = __float_as_uint(B0[4*LDX1]);
                mma8(ctxacc[nb], a, b);
            }
            if (db == 1) {
                uint32_t b[2];
                const float* B0 = kv_s + (kk + t4)*LDX1 + 128 + gid;
                b[0] = __float_as_uint(B0[0]);
                b[1] = __float_as_uint(B0[4*LDX1]);
                mma8(ksacc, a, b);
            }
        }
    }

    float* cg = g_ctx_part[ls] + ((size_t)bh*MM + mt*TM)*DD;
    #pragma unroll
    for (int nb = 0; nb < 8; nb++) {
        int m0 = mb*16 + gid;
        int d  = db*64 + nb*8 + 2*t4;
        *(float2*)&cg[m0*DD + d]       = make_float2(ctxacc[nb][0], ctxacc[nb][1]);
        *(float2*)&cg[(m0 + 8)*DD + d] = make_float2(ctxacc[nb][2], ctxacc[nb][3]);
    }
    if (db == 1 && t4 == 0) {
        g_ksum_part[ls][bh*MM + mt*TM + mb*16 + gid]     = ksacc[0];
        g_ksum_part[ls][bh*MM + mt*TM + mb*16 + gid + 8] = ksacc[2];
    }
}

// ---------------------------------------------------------------------------
// KRED: g_ctx = sum of 8 partials; g_ksum likewise
// ---------------------------------------------------------------------------
__global__ __launch_bounds__(256) void kred_kernel()
{
    int i = blockIdx.x*256 + threadIdx.x;
    if (i < N4CTX) {
        float4 s = ((const float4*)g_ctx_part[0])[i];
        #pragma unroll
        for (int p = 1; p < NSPL; p++) {
            float4 a = ((const float4*)g_ctx_part[p])[i];
            s.x += a.x; s.y += a.y; s.z += a.z; s.w += a.w;
        }
        ((float4*)g_ctx)[i] = s;
    } else {
        int j = i - N4CTX;
        float4 s = ((const float4*)g_ksum_part[0])[j];
        #pragma unroll
        for (int p = 1; p < NSPL; p++) {
            float4 a = ((const float4*)g_ksum_part[p])[j];
            s.x += a.x; s.y += a.y; s.z += a.z; s.w += a.w;
        }
        ((float4*)g_ksum)[j] = s;
    }
}

// ===================== K2 (R8-256 + permuted Q a-frags) =====================
__device__ __forceinline__ void cp_tile2(uint32_t sbase, const float* g, int t) {
    #pragma unroll
    for (int r = 0; r < 8; r++) {
        int i = t + r*256;
        uint32_t saddr = sbase + (((i >> 5)*LDX2 + (i & 31)*4) << 2);
        asm volatile("cp.async.cg.shared.global [%0], [%1], 16;"
                     :: "r"(saddr), "l"(g + 4*i));
    }
}

__global__ __launch_bounds__(256, 1) void k2_out_kernel(
    const float* __restrict__ qin, const float* __restrict__ proj,
    float* __restrict__ out)
{
    extern __shared__ float sm[];
    float* q_s   = sm;                  // [128][136]  Q (perm, RNA, persistent)
    float* p_buf = q_s + TL2*LDX1;      // [64][140]   P chunk (cp.async)
    float* c_buf = p_buf + TM*LDX2;     // [64][140]   ctx chunk (cp.async) + ks col
    float* phi_s = c_buf + TM*LDX2;     // [128 l][68 m]
    float* g_s   = phi_s + TL2*PT2;     // [128]
    float* dinv  = g_s + TL2;           // [128]

    const int bh = blockIdx.x / NLT2;
    const int lt = blockIdx.x % NLT2;
    const int t  = threadIdx.x;
    const int w  = t >> 5, lane = t & 31;
    const int gid = lane >> 2, t4 = lane & 3;

    const uint32_t pb_u = (uint32_t)__cvta_generic_to_shared(p_buf);
    const uint32_t cb_u = (uint32_t)__cvta_generic_to_shared(c_buf);

    cp_tile2(pb_u, proj, t);
    asm volatile("cp.async.commit_group;");

    // Q tile 128x128: permuted LDX1 layout, fp32 g via warp reduce, RNA tf32
    {
        const float* Qg = qin + ((size_t)bh*LTOT + lt*TL2)*DD;
        #pragma unroll
        for (int r = 0; r < 16; r++) load_perm_g(q_s, g_s, Qg, t + r*256, lane);
    }

    const int lb = w & 3;     // l-block of 32
    const int mh = w >> 2;    // GEMM A: m-half
    const int db = w >> 2;    // GEMM B: d-half

    float oacc[2][8][4];
    #pragma unroll
    for (int ia = 0; ia < 2; ia++)
        #pragma unroll
        for (int nb = 0; nb < 8; nb++)
            #pragma unroll
            for (int i = 0; i < 4; i++) oacc[ia][nb][i] = 0.f;
    float dks[2][4];
    #pragma unroll
    for (int ia = 0; ia < 2; ia++)
        #pragma unroll
        for (int i = 0; i < 4; i++) dks[ia][i] = 0.f;

    for (int mc = 0; mc < NMT; mc++) {
        __syncthreads();   // prev GEMM B done; q/g stores visible (first iter)
        cp_tile2(cb_u, g_ctx + ((size_t)bh*MM + mc*TM)*DD, t);
        asm volatile("cp.async.commit_group;");        // group C[mc]
        asm volatile("cp.async.wait_group 1;");        // P[mc] arrived
        __syncthreads();                               // p_buf published

        // GEMM A: S[128l x 64m] = Q @ P_chunk^T ; warp 32l x 32m; LDS.64 a-frags
        float c[2][4][4];
        #pragma unroll
        for (int ia = 0; ia < 2; ia++)
            #pragma unroll
            for (int nb = 0; nb < 4; nb++)
                #pragma unroll
                for (int i = 0; i < 4; i++) c[ia][nb][i] = 0.f;
        #pragma unroll
        for (int kk = 0; kk < DD; kk += 8) {
            uint32_t a[2][4], b[2];
            #pragma unroll
            for (int ia = 0; ia < 2; ia++)
                lda64(a[ia], q_s + (lb*32 + ia*16 + gid)*LDX1 + kk + 2*t4, LDX1);
            #pragma unroll
            for (int nb = 0; nb < 4; nb++) {
                const float* B0 = p_buf + (mh*32 + nb*8 + gid)*LDX2 + kk + t4;
                b[0] = __float_as_uint(B0[0]);
                b[1] = __float_as_uint(B0[4]);
                mma8(c[0][nb], a[0], b);
                mma8(c[1][nb], a[1], b);
            }
        }
        __syncthreads();   // p_buf reads done

        if (mc + 1 < NMT) cp_tile2(pb_u, proj + (size_t)((mc+1)*TM)*DD, t);
        asm volatile("cp.async.commit_group;");        // group P[mc+1]

        // exp -> phi_s[l][m] (plain layout)
        #pragma unroll
        for (int ia = 0; ia < 2; ia++)
            #pragma unroll
            for (int nb = 0; nb < 4; nb++) {
                int m0 = mh*32 + nb*8 + 2*t4;
                #pragma unroll
                for (int i = 0; i < 4; i++) {
                    int l = lb*32 + ia*16 + gid + ((i >> 1) << 3);
                    float ph = __expf(fmaf(c[ia][nb][i], INV_SSD, CADD - g_s[l]));
                    phi_s[l*PT2 + m0 + (i & 1)] = to_tf32(ph);
                }
            }
        if (t < TM) {
            float ks = to_tf32(g_ksum[bh*MM + mc*TM + t]);
            *(float4*)&c_buf[t*LDX2 + 128] = make_float4(ks, 0.f, 0.f, 0.f);
            *(float4*)&c_buf[t*LDX2 + 132] = make_float4(0.f, 0.f, 0.f, 0.f);
        }
        asm volatile("cp.async.wait_group 1;");        // C[mc] arrived
        __syncthreads();                               // c_buf + phi + ks published

        // GEMM B: out += phi(128x64) @ ctx(64x128); warp 32l x 64d; db==1 ks col
        #pragma unroll
        for (int kk = 0; kk < TM; kk += 8) {
            uint32_t a[2][4];
            #pragma unroll
            for (int ia = 0; ia < 2; ia++)
                lda32(a[ia], phi_s + (lb*32 + ia*16 + gid)*PT2 + kk + t4, PT2);
            #pragma unroll
            for (int nb = 0; nb < 8; nb++) {
                uint32_t b[2];
                const float* B0 = c_buf + (kk + t4)*LDX2 + db*64 + nb*8 + gid;
                b[0] = __float_as_uint(B0[0]);
                b[1] = __float_as_uint(B0[4*LDX2]);
                mma8(oacc[0][nb], a[0], b);
                mma8(oacc[1][nb], a[1], b);
            }
            if (db == 1) {
                uint32_t b[2];
                const float* B0 = c_buf + (kk + t4)*LDX2 + 128 + gid;
                b[0] = __float_as_uint(B0[0]);
                b[1] = __float_as_uint(B0[4*LDX2]);
                mma8(dks[0], a[0], b);
                mma8(dks[1], a[1], b);
            }
        }
    }

    if (db == 1 && t4 == 0) {
        #pragma unroll
        for (int ia = 0; ia < 2; ia++) {
            int l = lb*32 + ia*16 + gid;
            dinv[l]     = 1.0f / dks[ia][0];
            dinv[l + 8] = 1.0f / dks[ia][2];
        }
    }
    __syncthreads();

    float* og = out + ((size_t)bh*LTOT + lt*TL2)*DD;
    #pragma unroll
    for (int ia = 0; ia < 2; ia++)
        #pragma unroll
        for (int nb = 0; nb < 8; nb++) {
            int l0 = lb*32 + ia*16 + gid;
            int d  = db*64 + nb*8 + 2*t4;
            float i0 = dinv[l0], i1 = dinv[l0 + 8];
            *(float2*)&og[l0*DD + d]       = make_float2(oacc[ia][nb][0]*i0, oacc[ia][nb][1]*i0);
            *(float2*)&og[(l0 + 8)*DD + d] = make_float2(oacc[ia][nb][2]*i1, oacc[ia][nb][3]*i1);
        }
}

extern "C" void kernel_launch(void* const* d_in, const int* in_sizes, int n_in,
                              void* d_out, int out_size) {
    const float* q    = (const float*)d_in[0];
    const float* k    = (const float*)d_in[1];
    const float* v    = (const float*)d_in[2];
    const float* proj = (const float*)d_in[3];
    float* out = (float*)d_out;

    size_t smem1 = (TL*LDX1 + TM*LDX1 + TM*PT1 + 64) * sizeof(float);              // ~86.3 KB
    size_t smem2 = (TL2*LDX1 + 2*TM*LDX2 + TL2*PT2 + TL2 + TL2) * sizeof(float);   // ~177 KB
    cudaFuncSetAttribute(k1_ctx_kernel, cudaFuncAttributeMaxDynamicSharedMemorySize, (int)smem1);
    cudaFuncSetAttribute(k2_out_kernel, cudaFuncAttributeMaxDynamicSharedMemorySize, (int)smem2);

    k1_ctx_kernel<<<BH * NMT * NSPL, 256, smem1>>>(k, v, proj);
    kred_kernel<<<(N4CTX + N4KS) / 256, 256>>>();
    k2_out_kernel<<<BH * NLT2, 256, smem2>>>(q, proj, out);
}

// round 16
// speedup vs baseline: 1.2253x; 1.0424x over previous
#include <cuda_runtime.h>
#include <cstdint>

#define BH   32
#define LTOT 4096
#define DD   128
#define MM   640
#define TL   64
#define TM   64
#define NMT  (MM/TM)    // 10
#define NLT  (LTOT/TL)  // 64
#define NSPL 8          // k1 L-split
#define CHK  (NLT/NSPL) // 8 chunks per k1 block
#define TL2  128
#define NLT2 (LTOT/TL2) // 32
#define LDX1 136        // k1 permuted-layout stride
#define PT1  72
#define LDX2 140        // k2 plain strides (Q, P)
#define CT2  72         // k2 transposed-ctx + phi stride (72 mod 32 == 8)

#define N4CTX (BH*MM*DD/4)  // 655360
#define N4KS  (BH*MM/4)     // 5120

#define INV_SSD  0.2973017787506803f
#define INV2SQD  0.04419417382415922f
#define CADD    -3.2306341575510305f

// g_ctx semantic: [bh][d 0..127][pcol(m) 0..639]  (transposed + m-pair permuted)
__device__ float g_ctx[(size_t)BH * MM * DD];
__device__ float g_ksum[BH * MM];
// partials semantic: [p][bh][d][m] (transposed, unpermuted)
__device__ float g_ctx_part[NSPL][(size_t)BH * MM * DD];
__device__ float g_ksum_part[NSPL][BH * MM];

__device__ __forceinline__ float to_tf32(float x) {
    uint32_t u;
    asm("cvt.rna.tf32.f32 %0, %1;" : "=r"(u) : "f"(x));
    return __uint_as_float(u);
}

__device__ __forceinline__ int pcol(int k) {
    return (k & ~7) | ((k & 3) << 1) | ((k >> 2) & 1);
}

__device__ __forceinline__ void mma8(float* c, const uint32_t* a, const uint32_t* b) {
    asm volatile(
        "mma.sync.aligned.m16n8k8.row.col.f32.tf32.tf32.f32 "
        "{%0,%1,%2,%3},{%4,%5,%6,%7},{%8,%9},{%0,%1,%2,%3};\n"
        : "+f"(c[0]), "+f"(c[1]), "+f"(c[2]), "+f"(c[3])
        : "r"(a[0]), "r"(a[1]), "r"(a[2]), "r"(a[3]), "r"(b[0]), "r"(b[1]));
}

// ============ k1 permuted-layout helpers (stride LDX1) ======================
__device__ __forceinline__ void load_perm(float* dst, const float* src, int i) {
    int row = i >> 5, c = i & 31;
    const float* g = src + row*DD + (c >> 1)*8 + (c & 1)*2;
    float2 u = *(const float2*)g;
    float2 w = *(const float2*)(g + 4);
    float4 o;
    o.x = to_tf32(u.x); o.y = to_tf32(w.x); o.z = to_tf32(u.y); o.w = to_tf32(w.y);
    *(float4*)&dst[row*LDX1 + c*4] = o;
}

__device__ __forceinline__ void load_perm_g(float* dst, float* g_s, const float* src,
                                            int i, int lane) {
    int row = i >> 5, c = i & 31;
    const float* g = src + row*DD + (c >> 1)*8 + (c & 1)*2;
    float2 u = *(const float2*)g;
    float2 w = *(const float2*)(g + 4);
    float ss = u.x*u.x + u.y*u.y + w.x*w.x + w.y*w.y;
    ss += __shfl_xor_sync(0xffffffffu, ss, 16);
    ss += __shfl_xor_sync(0xffffffffu, ss, 8);
    ss += __shfl_xor_sync(0xffffffffu, ss, 4);
    ss += __shfl_xor_sync(0xffffffffu, ss, 2);
    ss += __shfl_xor_sync(0xffffffffu, ss, 1);
    if (lane == 0) g_s[row] = ss * INV2SQD;
    float4 o;
    o.x = to_tf32(u.x); o.y = to_tf32(w.x); o.z = to_tf32(u.y); o.w = to_tf32(w.y);
    *(float4*)&dst[row*LDX1 + c*4] = o;
}

__device__ __forceinline__ void load_plain1(float* dst, const float4* src, int i) {
    float4 v = src[i];
    v.x = to_tf32(v.x); v.y = to_tf32(v.y); v.z = to_tf32(v.z); v.w = to_tf32(v.w);
    *(float4*)&dst[(i >> 5)*LDX1 + (i & 31)*4] = v;
}

__device__ __forceinline__ void lda64(uint32_t* a, const float* A0, int rstride) {
    float2 x0 = *(const float2*)A0;
    float2 x1 = *(const float2*)(A0 + 8*rstride);
    a[0] = __float_as_uint(x0.x); a[1] = __float_as_uint(x1.x);
    a[2] = __float_as_uint(x0.y); a[3] = __float_as_uint(x1.y);
}

__device__ __forceinline__ void lda32(uint32_t* a, const float* A0, int rstride) {
    a[0] = __float_as_uint(A0[0]);
    a[1] = __float_as_uint(A0[8*rstride]);
    a[2] = __float_as_uint(A0[4]);
    a[3] = __float_as_uint(A0[8*rstride + 4]);
}

// ---------------------------------------------------------------------------
// K1 (R7-exact compute; epilogue stores partials TRANSPOSED [d][m])
// ---------------------------------------------------------------------------
__global__ __launch_bounds__(256, 2) void k1_ctx_kernel(
    const float* __restrict__ kin, const float* __restrict__ vin,
    const float* __restrict__ proj)
{
    extern __shared__ float sm[];
    float* kv_s = sm;                // [64][136]
    float* p_s  = kv_s + TL*LDX1;    // [64][136]
    float* phiT = p_s  + TM*LDX1;    // [64 m][72]
    float* g_s  = phiT + TM*PT1;     // [64]

    const int bx = blockIdx.x;
    const int bh = bx / (NMT*NSPL);
    const int rr = bx % (NMT*NSPL);
    const int mt = rr / NSPL;
    const int ls = rr % NSPL;
    const int t  = threadIdx.x;
    const int w  = t >> 5, lane = t & 31;
    const int gid = lane >> 2, t4 = lane & 3;

    {
        const float* Pg = proj + (size_t)(mt*TM)*DD;
        #pragma unroll
        for (int r = 0; r < 8; r++) load_perm(p_s, Pg, t + r*256);
    }
    if (t < TL) {
        *(float4*)&kv_s[t*LDX1 + 128] = make_float4(1.f, 0.f, 0.f, 0.f);
        *(float4*)&kv_s[t*LDX1 + 132] = make_float4(0.f, 0.f, 0.f, 0.f);
    }

    const float* kg = kin + (size_t)bh*LTOT*DD;
    const float* vg = vin + (size_t)bh*LTOT*DD;

    const int lb = w & 3, mh = w >> 2;
    const int mb = w & 3, db = w >> 2;

    float ctxacc[8][4];
    #pragma unroll
    for (int nb = 0; nb < 8; nb++)
        #pragma unroll
        for (int i = 0; i < 4; i++) ctxacc[nb][i] = 0.f;
    float ksacc[4] = {0.f, 0.f, 0.f, 0.f};

    for (int lc = ls*CHK; lc < ls*CHK + CHK; lc++) {
        __syncthreads();
        {
            const float* Kg = kg + (size_t)lc*TL*DD;
            #pragma unroll
            for (int r = 0; r < 8; r++) load_perm_g(kv_s, g_s, Kg, t + r*256, lane);
        }
        __syncthreads();

        float c[4][4];
        #pragma unroll
        for (int nb = 0; nb < 4; nb++)
            #pragma unroll
            for (int i = 0; i < 4; i++) c[nb][i] = 0.f;
        #pragma unroll
        for (int kk = 0; kk < DD; kk += 8) {
            uint32_t a[4], b[2];
            lda64(a, kv_s + (lb*16 + gid)*LDX1 + kk + 2*t4, LDX1);
            #pragma unroll
            for (int nb = 0; nb < 4; nb++) {
                float2 y = *(const float2*)(p_s + (mh*32 + nb*8 + gid)*LDX1 + kk + 2*t4);
                b[0] = __float_as_uint(y.x); b[1] = __float_as_uint(y.y);
                mma8(c[nb], a, b);
            }
        }
        __syncthreads();

        #pragma unroll
        for (int nb = 0; nb < 4; nb++) {
            int m0 = mh*32 + nb*8 + 2*t4;
            #pragma unroll
            for (int i = 0; i < 4; i++) {
                int l = lb*16 + gid + ((i >> 1) << 3);
                float ph = __expf(fmaf(c[nb][i], INV_SSD, CADD - g_s[l]));
                phiT[(m0 + (i & 1))*PT1 + pcol(l)] = to_tf32(ph);
            }
        }
        {
            const float4* Vg = (const float4*)(vg + (size_t)lc*TL*DD);
            #pragma unroll
            for (int r = 0; r < 8; r++) load_plain1(kv_s, Vg, t + r*256);
        }
        __syncthreads();

        #pragma unroll
        for (int kk = 0; kk < TL; kk += 8) {
            uint32_t a[4];
            lda64(a, phiT + (mb*16 + gid)*PT1 + kk + 2*t4, PT1);
            #pragma unroll
            for (int nb = 0; nb < 8; nb++) {
                uint32_t b[2];
                const float* B0 = kv_s + (kk + t4)*LDX1 + db*64 + nb*8 + gid;
                b[0] = __float_as_uint(B0[0]);
                b[1] = __float_as_uint(B0[4*LDX1]);
                mma8(ctxacc[nb], a, b);
            }
            if (db == 1) {
                uint32_t b[2];
                const float* B0 = kv_s + (kk + t4)*LDX1 + 128 + gid;
                b[0] = __float_as_uint(B0[0]);
                b[1] = __float_as_uint(B0[4*LDX1]);
                mma8(ksacc, a, b);
            }
        }
    }

    // epilogue: write TRANSPOSED partial [d][m] (coalesced 32B runs per instr)
    {
        float* cgT = g_ctx_part[ls] + (size_t)bh*MM*DD;
        int m0g = mt*TM + mb*16 + gid;
        #pragma unroll
        for (int nb = 0; nb < 8; nb++) {
            int d0 = db*64 + nb*8 + 2*t4;
            cgT[(size_t)d0*MM + m0g]           = ctxacc[nb][0];
            cgT[(size_t)(d0+1)*MM + m0g]       = ctxacc[nb][1];
            cgT[(size_t)d0*MM + m0g + 8]       = ctxacc[nb][2];
            cgT[(size_t)(d0+1)*MM + m0g + 8]   = ctxacc[nb][3];
        }
    }
    if (db == 1 && t4 == 0) {
        g_ksum_part[ls][bh*MM + mt*TM + mb*16 + gid]     = ksacc[0];
        g_ksum_part[ls][bh*MM + mt*TM + mb*16 + gid + 8] = ksacc[2];
    }
}

// ---------------------------------------------------------------------------
// KRED: sum partials; ctx written with pcol(m) permutation (stride-2 scatter)
// ---------------------------------------------------------------------------
__global__ __launch_bounds__(256) void kred_kernel()
{
    int i = blockIdx.x*256 + threadIdx.x;
    if (i < N4CTX) {
        float4 s = ((const float4*)g_ctx_part[0])[i];
        #pragma unroll
        for (int p = 1; p < NSPL; p++) {
            float4 a = ((const float4*)g_ctx_part[p])[i];
            s.x += a.x; s.y += a.y; s.z += a.z; s.w += a.w;
        }
        int m0  = (i % (MM/4)) * 4;            // 4-aligned m within row
        int row = i / (MM/4);                  // bh*128 + d
        float* out = g_ctx + (size_t)row*MM;
        int col0 = (m0 & ~7) + ((m0 & 4) ? 1 : 0);
        out[col0]     = s.x;
        out[col0 + 2] = s.y;
        out[col0 + 4] = s.z;
        out[col0 + 6] = s.w;
    } else {
        int j = i - N4CTX;
        float4 s = ((const float4*)g_ksum_part[0])[j];
        #pragma unroll
        for (int p = 1; p < NSPL; p++) {
            float4 a = ((const float4*)g_ksum_part[p])[j];
            s.x += a.x; s.y += a.y; s.z += a.z; s.w += a.w;
        }
        ((float4*)g_ksum)[j] = s;
    }
}

// ===================== K2 (R8 base; GEMM B all-LDS.64 via transposed ctx) ===
__device__ __forceinline__ void cp_tileP(uint32_t sbase, const float* g, int t) {
    #pragma unroll
    for (int r = 0; r < 8; r++) {
        int i = t + r*256;
        uint32_t saddr = sbase + (((i >> 5)*LDX2 + (i & 31)*4) << 2);
        asm volatile("cp.async.cg.shared.global [%0], [%1], 16;"
                     :: "r"(saddr), "l"(g + 4*i));
    }
}

// transposed ctx chunk: 128 d-rows x 64 m-cols from 640-wide rows
__device__ __forceinline__ void cp_tileC(uint32_t sbase, const float* g, int t) {
    #pragma unroll
    for (int r = 0; r < 8; r++) {
        int i = t + r*256;                 // 0..2047
        int d = i >> 4, c = i & 15;        // 16 float4 per row
        uint32_t saddr = sbase + ((d*CT2 + c*4) << 2);
        asm volatile("cp.async.cg.shared.global [%0], [%1], 16;"
                     :: "r"(saddr), "l"(g + (size_t)d*MM + c*4));
    }
}

__global__ __launch_bounds__(256, 1) void k2_out_kernel(
    const float* __restrict__ qin, const float* __restrict__ proj,
    float* __restrict__ out)
{
    extern __shared__ float sm[];
    float* q_s   = sm;                  // [128][140]  Q (plain, RNA, persistent)
    float* p_buf = q_s + TL2*LDX2;      // [64][140]   P chunk (cp.async)
    float* c_buf = p_buf + TM*LDX2;     // [136][72]   ctx^T chunk + ks row 128 + zeros
    float* phi_s = c_buf + 136*CT2;     // [128 l][72] phi, m at pcol positions
    float* g_s   = phi_s + TL2*CT2;     // [128]
    float* dinv  = g_s + TL2;           // [128]

    const int bh = blockIdx.x / NLT2;
    const int lt = blockIdx.x % NLT2;
    const int t  = threadIdx.x;
    const int w  = t >> 5, lane = t & 31;
    const int gid = lane >> 2, t4 = lane & 3;

    const uint32_t pb_u = (uint32_t)__cvta_generic_to_shared(p_buf);
    const uint32_t cb_u = (uint32_t)__cvta_generic_to_shared(c_buf);

    cp_tileP(pb_u, proj, t);
    asm volatile("cp.async.commit_group;");

    // zero ks-neighbor rows 129..135 once (never touched by cp.async)
    for (int z = t; z < 7*CT2; z += 256) c_buf[129*CT2 + z] = 0.f;

    // Q tile 128x128 + g (fp32 via warp reduce during load) — R8-exact
    {
        const float4* Qg = (const float4*)(qin + ((size_t)bh*LTOT + lt*TL2)*DD);
        #pragma unroll
        for (int r = 0; r < 16; r++) {
            int i = t + r*256;
            float4 v = Qg[i];
            float ss = v.x*v.x + v.y*v.y + v.z*v.z + v.w*v.w;
            ss += __shfl_xor_sync(0xffffffffu, ss, 16);
            ss += __shfl_xor_sync(0xffffffffu, ss, 8);
            ss += __shfl_xor_sync(0xffffffffu, ss, 4);
            ss += __shfl_xor_sync(0xffffffffu, ss, 2);
            ss += __shfl_xor_sync(0xffffffffu, ss, 1);
            if (lane == 0) g_s[i >> 5] = ss * INV2SQD;
            v.x = to_tf32(v.x); v.y = to_tf32(v.y); v.z = to_tf32(v.z); v.w = to_tf32(v.w);
            *(float4*)&q_s[(i>>5)*LDX2 + (i&31)*4] = v;
        }
    }

    const int lb = w & 3;     // l-block of 32
    const int mh = w >> 2;    // GEMM A: m-half
    const int db = w >> 2;    // GEMM B: d-half

    float oacc[2][8][4];
    #pragma unroll
    for (int ia = 0; ia < 2; ia++)
        #pragma unroll
        for (int nb = 0; nb < 8; nb++)
            #pragma unroll
            for (int i = 0; i < 4; i++) oacc[ia][nb][i] = 0.f;
    float dks[2][4];
    #pragma unroll
    for (int ia = 0; ia < 2; ia++)
        #pragma unroll
        for (int i = 0; i < 4; i++) dks[ia][i] = 0.f;

    for (int mc = 0; mc < NMT; mc++) {
        __syncthreads();
        cp_tileC(cb_u, g_ctx + (size_t)bh*MM*DD + mc*TM, t);
        asm volatile("cp.async.commit_group;");        // group C[mc]
        asm volatile("cp.async.wait_group 1;");        // P[mc] arrived
        __syncthreads();                               // p_buf published

        // GEMM A: S[128l x 64m] = Q @ P_chunk^T — R8-exact
        float c[2][4][4];
        #pragma unroll
        for (int ia = 0; ia < 2; ia++)
            #pragma unroll
            for (int nb = 0; nb < 4; nb++)
                #pragma unroll
                for (int i = 0; i < 4; i++) c[ia][nb][i] = 0.f;
        #pragma unroll
        for (int kk = 0; kk < DD; kk += 8) {
            uint32_t a[2][4], b[2];
            #pragma unroll
            for (int ia = 0; ia < 2; ia++)
                lda32(a[ia], q_s + (lb*32 + ia*16 + gid)*LDX2 + kk + t4, LDX2);
            #pragma unroll
            for (int nb = 0; nb < 4; nb++) {
                const float* B0 = p_buf + (mh*32 + nb*8 + gid)*LDX2 + kk + t4;
                b[0] = __float_as_uint(B0[0]);
                b[1] = __float_as_uint(B0[4]);
                mma8(c[0][nb], a[0], b);
                mma8(c[1][nb], a[1], b);
            }
        }
        __syncthreads();   // p_buf reads done

        if (mc + 1 < NMT) cp_tileP(pb_u, proj + (size_t)((mc+1)*TM)*DD, t);
        asm volatile("cp.async.commit_group;");        // group P[mc+1]

        // exp -> phi_s[l][pcol(m)]
        #pragma unroll
        for (int ia = 0; ia < 2; ia++)
            #pragma unroll
            for (int nb = 0; nb < 4; nb++) {
                int m0 = mh*32 + nb*8 + 2*t4;
                #pragma unroll
                for (int i = 0; i < 4; i++) {
                    int l = lb*32 + ia*16 + gid + ((i >> 1) << 3);
                    float ph = __expf(fmaf(c[ia][nb][i], INV_SSD, CADD - g_s[l]));
                    phi_s[l*CT2 + pcol(m0 + (i & 1))] = to_tf32(ph);
                }
            }
        if (t < TM) {   // ks row at d=128, pcol'd m
            float ks = to_tf32(g_ksum[bh*MM + mc*TM + t]);
            c_buf[128*CT2 + pcol(t)] = ks;
        }
        asm volatile("cp.async.wait_group 1;");        // C[mc] arrived
        __syncthreads();                               // c_buf + phi + ks published

        // GEMM B: out += phi(128l x 64m) @ ctx^T; all operands LDS.64
        #pragma unroll
        for (int kk = 0; kk < TM; kk += 8) {
            uint32_t a[2][4];
            #pragma unroll
            for (int ia = 0; ia < 2; ia++)
                lda64(a[ia], phi_s + (lb*32 + ia*16 + gid)*CT2 + kk + 2*t4, CT2);
            #pragma unroll
            for (int nb = 0; nb < 8; nb++) {
                uint32_t b[2];
                float2 y = *(const float2*)(c_buf + (db*64 + nb*8 + gid)*CT2 + kk + 2*t4);
                b[0] = __float_as_uint(y.x);
                b[1] = __float_as_uint(y.y);
                mma8(oacc[0][nb], a[0], b);
                mma8(oacc[1][nb], a[1], b);
            }
            if (db == 1) {
                uint32_t b[2];
                float2 y = *(const float2*)(c_buf + (128 + gid)*CT2 + kk + 2*t4);
                b[0] = __float_as_uint(y.x);
                b[1] = __float_as_uint(y.y);
                mma8(dks[0], a[0], b);
                mma8(dks[1], a[1], b);
            }
        }
    }

    if (db == 1 && t4 == 0) {
        #pragma unroll
        for (int ia = 0; ia < 2; ia++) {
            int l = lb*32 + ia*16 + gid;
            dinv[l]     = 1.0f / dks[ia][0];
            dinv[l + 8] = 1.0f / dks[ia][2];
        }
    }
    __syncthreads();

    float* og = out + ((size_t)bh*LTOT + lt*TL2)*DD;
    #pragma unroll
    for (int ia = 0; ia < 2; ia++)
        #pragma unroll
        for (int nb = 0; nb < 8; nb++) {
            int l0 = lb*32 + ia*16 + gid;
            int d  = db*64 + nb*8 + 2*t4;
            float i0 = dinv[l0], i1 = dinv[l0 + 8];
            *(float2*)&og[l0*DD + d]       = make_float2(oacc[ia][nb][0]*i0, oacc[ia][nb][1]*i0);
            *(float2*)&og[(l0 + 8)*DD + d] = make_float2(oacc[ia][nb][2]*i1, oacc[ia][nb][3]*i1);
        }
}

extern "C" void kernel_launch(void* const* d_in, const int* in_sizes, int n_in,
                              void* d_out, int out_size) {
    const float* q    = (const float*)d_in[0];
    const float* k    = (const float*)d_in[1];
    const float* v    = (const float*)d_in[2];
    const float* proj = (const float*)d_in[3];
    float* out = (float*)d_out;

    size_t smem1 = (TL*LDX1 + TM*LDX1 + TM*PT1 + 64) * sizeof(float);               // ~86.3 KB
    size_t smem2 = (TL2*LDX2 + TM*LDX2 + 136*CT2 + TL2*CT2 + TL2 + TL2) * sizeof(float); // ~184.6 KB
    cudaFuncSetAttribute(k1_ctx_kernel, cudaFuncAttributeMaxDynamicSharedMemorySize, (int)smem1);
    cudaFuncSetAttribute(k2_out_kernel, cudaFuncAttributeMaxDynamicSharedMemorySize, (int)smem2);

    k1_ctx_kernel<<<BH * NMT * NSPL, 256, smem1>>>(k, v, proj);
    kred_kernel<<<(N4CTX + N4KS) / 256, 256>>>();
    k2_out_kernel<<<BH * NLT2, 256, smem2>>>(q, proj, out);
}

// round 17
// speedup vs baseline: 1.2346x; 1.0076x over previous
#include <cuda_runtime.h>
#include <cstdint>

#define BH   32
#define LTOT 4096
#define DD   128
#define MM   640
#define TL   64
#define TM   64
#define NMT  (MM/TM)    // 10
#define NLT  (LTOT/TL)  // 64
#define NSPL 8          // k1 L-split
#define CHK  (NLT/NSPL) // 8 chunks per k1 block
#define TL2  128
#define NLT2 (LTOT/TL2) // 32
#define LDX1 136        // k1 permuted-layout stride
#define PT1  72
#define LDX2 140        // k2 Q stride (plain)
#define LDXP 136        // k2 P chunk stride (permuted, LDS.64-bijective)
#define CT2  72         // k2 transposed-ctx + phi stride (72 mod 32 == 8)

#define N8CTX (BH*MM*DD/8)  // 327680
#define N4KS  (BH*MM/4)     // 5120

#define INV_SSD  0.2973017787506803f
#define INV2SQD  0.04419417382415922f
#define CADD    -3.2306341575510305f

// g_ctx semantic: [bh][d 0..127][pcol(m) 0..639]  (transposed + m-pair permuted)
__device__ float g_ctx[(size_t)BH * MM * DD];
__device__ float g_ksum[BH * MM];
// partials semantic: [p][bh][d][m] (transposed, unpermuted)
__device__ float g_ctx_part[NSPL][(size_t)BH * MM * DD];
__device__ float g_ksum_part[NSPL][BH * MM];
// P with k-pair permuted columns: g_projP[m][pcol(k)] = proj[m][k]
__device__ float g_projP[MM * DD];

__device__ __forceinline__ float to_tf32(float x) {
    uint32_t u;
    asm("cvt.rna.tf32.f32 %0, %1;" : "=r"(u) : "f"(x));
    return __uint_as_float(u);
}

__device__ __forceinline__ int pcol(int k) {
    return (k & ~7) | ((k & 3) << 1) | ((k >> 2) & 1);
}

__device__ __forceinline__ void mma8(float* c, const uint32_t* a, const uint32_t* b) {
    asm volatile(
        "mma.sync.aligned.m16n8k8.row.col.f32.tf32.tf32.f32 "
        "{%0,%1,%2,%3},{%4,%5,%6,%7},{%8,%9},{%0,%1,%2,%3};\n"
        : "+f"(c[0]), "+f"(c[1]), "+f"(c[2]), "+f"(c[3])
        : "r"(a[0]), "r"(a[1]), "r"(a[2]), "r"(a[3]), "r"(b[0]), "r"(b[1]));
}

// ============ k1 permuted-layout helpers (stride LDX1) ======================
__device__ __forceinline__ void load_perm(float* dst, const float* src, int i) {
    int row = i >> 5, c = i & 31;
    const float* g = src + row*DD + (c >> 1)*8 + (c & 1)*2;
    float2 u = *(const float2*)g;
    float2 w = *(const float2*)(g + 4);
    float4 o;
    o.x = to_tf32(u.x); o.y = to_tf32(w.x); o.z = to_tf32(u.y); o.w = to_tf32(w.y);
    *(float4*)&dst[row*LDX1 + c*4] = o;
}

__device__ __forceinline__ void load_perm_g(float* dst, float* g_s, const float* src,
                                            int i, int lane) {
    int row = i >> 5, c = i & 31;
    const float* g = src + row*DD + (c >> 1)*8 + (c & 1)*2;
    float2 u = *(const float2*)g;
    float2 w = *(const float2*)(g + 4);
    float ss = u.x*u.x + u.y*u.y + w.x*w.x + w.y*w.y;
    ss += __shfl_xor_sync(0xffffffffu, ss, 16);
    ss += __shfl_xor_sync(0xffffffffu, ss, 8);
    ss += __shfl_xor_sync(0xffffffffu, ss, 4);
    ss += __shfl_xor_sync(0xffffffffu, ss, 2);
    ss += __shfl_xor_sync(0xffffffffu, ss, 1);
    if (lane == 0) g_s[row] = ss * INV2SQD;
    float4 o;
    o.x = to_tf32(u.x); o.y = to_tf32(w.x); o.z = to_tf32(u.y); o.w = to_tf32(w.y);
    *(float4*)&dst[row*LDX1 + c*4] = o;
}

__device__ __forceinline__ void load_plain1(float* dst, const float4* src, int i) {
    float4 v = src[i];
    v.x = to_tf32(v.x); v.y = to_tf32(v.y); v.z = to_tf32(v.z); v.w = to_tf32(v.w);
    *(float4*)&dst[(i >> 5)*LDX1 + (i & 31)*4] = v;
}

__device__ __forceinline__ void lda64(uint32_t* a, const float* A0, int rstride) {
    float2 x0 = *(const float2*)A0;
    float2 x1 = *(const float2*)(A0 + 8*rstride);
    a[0] = __float_as_uint(x0.x); a[1] = __float_as_uint(x1.x);
    a[2] = __float_as_uint(x0.y); a[3] = __float_as_uint(x1.y);
}

__device__ __forceinline__ void lda32(uint32_t* a, const float* A0, int rstride) {
    a[0] = __float_as_uint(A0[0]);
    a[1] = __float_as_uint(A0[8*rstride]);
    a[2] = __float_as_uint(A0[4]);
    a[3] = __float_as_uint(A0[8*rstride + 4]);
}

// ---------------------------------------------------------------------------
// KPREP: g_projP[m][pcol(k)] = proj[m][k]  (640x128, one-shot, ~3us)
// ---------------------------------------------------------------------------
__global__ __launch_bounds__(256) void kprep_kernel(const float* __restrict__ proj)
{
    int j = blockIdx.x*256 + threadIdx.x;     // 10240 groups of 8 k
    if (j < MM*DD/8) {
        const float4* src = (const float4*)proj + (size_t)j*2;
        float4 a0 = src[0], a1 = src[1];
        float4 o0 = make_float4(a0.x, a1.x, a0.y, a1.y);  // pos 0..3 = k0,k4,k1,k5
        float4 o1 = make_float4(a0.z, a1.z, a0.w, a1.w);  // pos 4..7 = k2,k6,k3,k7
        float4* dst = (float4*)g_projP + (size_t)j*2;
        dst[0] = o0; dst[1] = o1;
    }
}

// ---------------------------------------------------------------------------
// K1 (R7-exact compute; epilogue stores partials TRANSPOSED [d][m])
// ---------------------------------------------------------------------------
__global__ __launch_bounds__(256, 2) void k1_ctx_kernel(
    const float* __restrict__ kin, const float* __restrict__ vin,
    const float* __restrict__ proj)
{
    extern __shared__ float sm[];
    float* kv_s = sm;                // [64][136]
    float* p_s  = kv_s + TL*LDX1;    // [64][136]
    float* phiT = p_s  + TM*LDX1;    // [64 m][72]
    float* g_s  = phiT + TM*PT1;     // [64]

    const int bx = blockIdx.x;
    const int bh = bx / (NMT*NSPL);
    const int rr = bx % (NMT*NSPL);
    const int mt = rr / NSPL;
    const int ls = rr % NSPL;
    const int t  = threadIdx.x;
    const int w  = t >> 5, lane = t & 31;
    const int gid = lane >> 2, t4 = lane & 3;

    {
        const float* Pg = proj + (size_t)(mt*TM)*DD;
        #pragma unroll
        for (int r = 0; r < 8; r++) load_perm(p_s, Pg, t + r*256);
    }
    if (t < TL) {
        *(float4*)&kv_s[t*LDX1 + 128] = make_float4(1.f, 0.f, 0.f, 0.f);
        *(float4*)&kv_s[t*LDX1 + 132] = make_float4(0.f, 0.f, 0.f, 0.f);
    }

    const float* kg = kin + (size_t)bh*LTOT*DD;
    const float* vg = vin + (size_t)bh*LTOT*DD;

    const int lb = w & 3, mh = w >> 2;
    const int mb = w & 3, db = w >> 2;

    float ctxacc[8][4];
    #pragma unroll
    for (int nb = 0; nb < 8; nb++)
        #pragma unroll
        for (int i = 0; i < 4; i++) ctxacc[nb][i] = 0.f;
    float ksacc[4] = {0.f, 0.f, 0.f, 0.f};

    for (int lc = ls*CHK; lc < ls*CHK + CHK; lc++) {
        __syncthreads();
        {
            const float* Kg = kg + (size_t)lc*TL*DD;
            #pragma unroll
            for (int r = 0; r < 8; r++) load_perm_g(kv_s, g_s, Kg, t + r*256, lane);
        }
        __syncthreads();

        float c[4][4];
        #pragma unroll
        for (int nb = 0; nb < 4; nb++)
            #pragma unroll
            for (int i = 0; i < 4; i++) c[nb][i] = 0.f;
        #pragma unroll
        for (int kk = 0; kk < DD; kk += 8) {
            uint32_t a[4], b[2];
            lda64(a, kv_s + (lb*16 + gid)*LDX1 + kk + 2*t4, LDX1);
            #pragma unroll
            for (int nb = 0; nb < 4; nb++) {
                float2 y = *(const float2*)(p_s + (mh*32 + nb*8 + gid)*LDX1 + kk + 2*t4);
                b[0] = __float_as_uint(y.x); b[1] = __float_as_uint(y.y);
                mma8(c[nb], a, b);
            }
        }
        __syncthreads();

        #pragma unroll
        for (int nb = 0; nb < 4; nb++) {
            int m0 = mh*32 + nb*8 + 2*t4;
            #pragma unroll
            for (int i = 0; i < 4; i++) {
                int l = lb*16 + gid + ((i >> 1) << 3);
                float ph = __expf(fmaf(c[nb][i], INV_SSD, CADD - g_s[l]));
                phiT[(m0 + (i & 1))*PT1 + pcol(l)] = to_tf32(ph);
            }
        }
        {
            const float4* Vg = (const float4*)(vg + (size_t)lc*TL*DD);
            #pragma unroll
            for (int r = 0; r < 8; r++) load_plain1(kv_s, Vg, t + r*256);
        }
        __syncthreads();

        #pragma unroll
        for (int kk = 0; kk < TL; kk += 8) {
            uint32_t a[4];
            lda64(a, phiT + (mb*16 + gid)*PT1 + kk + 2*t4, PT1);
            #pragma unroll
            for (int nb = 0; nb < 8; nb++) {
                uint32_t b[2];
                const float* B0 = kv_s + (kk + t4)*LDX1 + db*64 + nb*8 + gid;
                b[0] = __float_as_uint(B0[0]);
                b[1] = __float_as_uint(B0[4*LDX1]);
                mma8(ctxacc[nb], a, b);
            }
            if (db == 1) {
                uint32_t b[2];
                const float* B0 = kv_s + (kk + t4)*LDX1 + 128 + gid;
                b[0] = __float_as_uint(B0[0]);
                b[1] = __float_as_uint(B0[4*LDX1]);
                mma8(ksacc, a, b);
            }
        }
    }

    // epilogue: write TRANSPOSED partial [d][m]
    {
        float* cgT = g_ctx_part[ls] + (size_t)bh*MM*DD;
        int m0g = mt*TM + mb*16 + gid;
        #pragma unroll
        for (int nb = 0; nb < 8; nb++) {
            int d0 = db*64 + nb*8 + 2*t4;
            cgT[(size_t)d0*MM + m0g]           = ctxacc[nb][0];
            cgT[(size_t)(d0+1)*MM + m0g]       = ctxacc[nb][1];
            cgT[(size_t)d0*MM + m0g + 8]       = ctxacc[nb][2];
            cgT[(size_t)(d0+1)*MM + m0g + 8]   = ctxacc[nb][3];
        }
    }
    if (db == 1 && t4 == 0) {
        g_ksum_part[ls][bh*MM + mt*TM + mb*16 + gid]     = ksacc[0];
        g_ksum_part[ls][bh*MM + mt*TM + mb*16 + gid + 8] = ksacc[2];
    }
}

// ---------------------------------------------------------------------------
// KRED: 8 m per thread; pcol permutation in registers -> 2x STG.128
// ---------------------------------------------------------------------------
__global__ __launch_bounds__(256) void kred_kernel()
{
    int i = blockIdx.x*256 + threadIdx.x;
    if (i < N8CTX) {
        int row = i / (MM/8);          // bh*128 + d
        int m0  = (i % (MM/8)) * 8;
        size_t off = (size_t)row*MM + m0;
        float4 s0 = *(const float4*)(g_ctx_part[0] + off);
        float4 s1 = *(const float4*)(g_ctx_part[0] + off + 4);
        #pragma unroll
        for (int p = 1; p < NSPL; p++) {
            float4 a0 = *(const float4*)(g_ctx_part[p] + off);
            float4 a1 = *(const float4*)(g_ctx_part[p] + off + 4);
            s0.x += a0.x; s0.y += a0.y; s0.z += a0.z; s0.w += a0.w;
            s1.x += a1.x; s1.y += a1.y; s1.z += a1.z; s1.w += a1.w;
        }
        // permuted positions: {m0, m4, m1, m5}, {m2, m6, m3, m7}
        float4 o0 = make_float4(s0.x, s1.x, s0.y, s1.y);
        float4 o1 = make_float4(s0.z, s1.z, s0.w, s1.w);
        *(float4*)(g_ctx + off)     = o0;
        *(float4*)(g_ctx + off + 4) = o1;
    } else {
        int j = i - N8CTX;             // < N4KS
        float4 s = ((const float4*)g_ksum_part[0])[j];
        #pragma unroll
        for (int p = 1; p < NSPL; p++) {
            float4 a = ((const float4*)g_ksum_part[p])[j];
            s.x += a.x; s.y += a.y; s.z += a.z; s.w += a.w;
        }
        ((float4*)g_ksum)[j] = s;
    }
}

// ===================== K2 (R16 base; GEMM A b-frags LDS.64 via g_projP) =====
__device__ __forceinline__ void cp_tileP(uint32_t sbase, const float* g, int t) {
    #pragma unroll
    for (int r = 0; r < 8; r++) {
        int i = t + r*256;
        uint32_t saddr = sbase + (((i >> 5)*LDXP + (i & 31)*4) << 2);
        asm volatile("cp.async.cg.shared.global [%0], [%1], 16;"
                     :: "r"(saddr), "l"(g + 4*i));
    }
}

// transposed ctx chunk: 128 d-rows x 64 m-cols from 640-wide rows
__device__ __forceinline__ void cp_tileC(uint32_t sbase, const float* g, int t) {
    #pragma unroll
    for (int r = 0; r < 8; r++) {
        int i = t + r*256;                 // 0..2047
        int d = i >> 4, c = i & 15;        // 16 float4 per row
        uint32_t saddr = sbase + ((d*CT2 + c*4) << 2);
        asm volatile("cp.async.cg.shared.global [%0], [%1], 16;"
                     :: "r"(saddr), "l"(g + (size_t)d*MM + c*4));
    }
}

__global__ __launch_bounds__(256, 1) void k2_out_kernel(
    const float* __restrict__ qin, const float* __restrict__ proj,
    float* __restrict__ out)
{
    extern __shared__ float sm[];
    float* q_s   = sm;                  // [128][140]  Q (plain, RNA, persistent)
    float* p_buf = q_s + TL2*LDX2;      // [64][136]   P chunk (cp.async, permuted)
    float* c_buf = p_buf + TM*LDXP;     // [136][72]   ctx^T chunk + ks row 128
    float* phi_s = c_buf + 136*CT2;     // [128 l][72] phi, m at pcol positions
    float* g_s   = phi_s + TL2*CT2;     // [128]
    float* dinv  = g_s + TL2;           // [128]

    const int bh = blockIdx.x / NLT2;
    const int lt = blockIdx.x % NLT2;
    const int t  = threadIdx.x;
    const int w  = t >> 5, lane = t & 31;
    const int gid = lane >> 2, t4 = lane & 3;

    const uint32_t pb_u = (uint32_t)__cvta_generic_to_shared(p_buf);
    const uint32_t cb_u = (uint32_t)__cvta_generic_to_shared(c_buf);

    cp_tileP(pb_u, g_projP, t);
    asm volatile("cp.async.commit_group;");

    // zero ks-neighbor rows 129..135 once
    for (int z = t; z < 7*CT2; z += 256) c_buf[129*CT2 + z] = 0.f;

    // Q tile 128x128 + g (fp32 via warp reduce during load)
    {
        const float4* Qg = (const float4*)(qin + ((size_t)bh*LTOT + lt*TL2)*DD);
        #pragma unroll
        for (int r = 0; r < 16; r++) {
            int i = t + r*256;
            float4 v = Qg[i];
            float ss = v.x*v.x + v.y*v.y + v.z*v.z + v.w*v.w;
            ss += __shfl_xor_sync(0xffffffffu, ss, 16);
            ss += __shfl_xor_sync(0xffffffffu, ss, 8);
            ss += __shfl_xor_sync(0xffffffffu, ss, 4);
            ss += __shfl_xor_sync(0xffffffffu, ss, 2);
            ss += __shfl_xor_sync(0xffffffffu, ss, 1);
            if (lane == 0) g_s[i >> 5] = ss * INV2SQD;
            v.x = to_tf32(v.x); v.y = to_tf32(v.y); v.z = to_tf32(v.z); v.w = to_tf32(v.w);
            *(float4*)&q_s[(i>>5)*LDX2 + (i&31)*4] = v;
        }
    }

    const int lb = w & 3;     // l-block of 32
    const int mh = w >> 2;    // GEMM A: m-half
    const int db = w >> 2;    // GEMM B: d-half

    float oacc[2][8][4];
    #pragma unroll
    for (int ia = 0; ia < 2; ia++)
        #pragma unroll
        for (int nb = 0; nb < 8; nb++)
            #pragma unroll
            for (int i = 0; i < 4; i++) oacc[ia][nb][i] = 0.f;
    float dks[2][4];
    #pragma unroll
    for (int ia = 0; ia < 2; ia++)
        #pragma unroll
        for (int i = 0; i < 4; i++) dks[ia][i] = 0.f;

    for (int mc = 0; mc < NMT; mc++) {
        __syncthreads();
        cp_tileC(cb_u, g_ctx + (size_t)bh*MM*DD + mc*TM, t);
        asm volatile("cp.async.commit_group;");        // group C[mc]
        asm volatile("cp.async.wait_group 1;");        // P[mc] arrived
        __syncthreads();                               // p_buf published

        // GEMM A: S[128l x 64m] = Q @ P_chunk^T ; b-frags LDS.64 (permuted P)
        float c[2][4][4];
        #pragma unroll
        for (int ia = 0; ia < 2; ia++)
            #pragma unroll
            for (int nb = 0; nb < 4; nb++)
                #pragma unroll
                for (int i = 0; i < 4; i++) c[ia][nb][i] = 0.f;
        #pragma unroll
        for (int kk = 0; kk < DD; kk += 8) {
            uint32_t a[2][4], b[2];
            #pragma unroll
            for (int ia = 0; ia < 2; ia++)
                lda32(a[ia], q_s + (lb*32 + ia*16 + gid)*LDX2 + kk + t4, LDX2);
            #pragma unroll
            for (int nb = 0; nb < 4; nb++) {
                float2 y = *(const float2*)(p_buf + (mh*32 + nb*8 + gid)*LDXP + kk + 2*t4);
                b[0] = __float_as_uint(y.x);
                b[1] = __float_as_uint(y.y);
                mma8(c[0][nb], a[0], b);
                mma8(c[1][nb], a[1], b);
            }
        }
        __syncthreads();   // p_buf reads done

        if (mc + 1 < NMT) cp_tileP(pb_u, g_projP + (size_t)((mc+1)*TM)*DD, t);
        asm volatile("cp.async.commit_group;");        // group P[mc+1]

        // exp -> phi_s[l][pcol(m)]
        #pragma unroll
        for (int ia = 0; ia < 2; ia++)
            #pragma unroll
            for (int nb = 0; nb < 4; nb++) {
                int m0 = mh*32 + nb*8 + 2*t4;
                #pragma unroll
                for (int i = 0; i < 4; i++) {
                    int l = lb*32 + ia*16 + gid + ((i >> 1) << 3);
                    float ph = __expf(fmaf(c[ia][nb][i], INV_SSD, CADD - g_s[l]));
                    phi_s[l*CT2 + pcol(m0 + (i & 1))] = to_tf32(ph);
                }
            }
        if (t < TM) {   // ks row at d=128, pcol'd m
            float ks = to_tf32(g_ksum[bh*MM + mc*TM + t]);
            c_buf[128*CT2 + pcol(t)] = ks;
        }
        asm volatile("cp.async.wait_group 1;");        // C[mc] arrived
        __syncthreads();                               // c_buf + phi + ks published

        // GEMM B: out += phi(128l x 64m) @ ctx^T; all operands LDS.64
        #pragma unroll
        for (int kk = 0; kk < TM; kk += 8) {
            uint32_t a[2][4];
            #pragma unroll
            for (int ia = 0; ia < 2; ia++)
                lda64(a[ia], phi_s + (lb*32 + ia*16 + gid)*CT2 + kk + 2*t4, CT2);
            #pragma unroll
            for (int nb = 0; nb < 8; nb++) {
                uint32_t b[2];
                float2 y = *(const float2*)(c_buf + (db*64 + nb*8 + gid)*CT2 + kk + 2*t4);
                b[0] = __float_as_uint(y.x);
                b[1] = __float_as_uint(y.y);
                mma8(oacc[0][nb], a[0], b);
                mma8(oacc[1][nb], a[1], b);
            }
            if (db == 1) {
                uint32_t b[2];
                float2 y = *(const float2*)(c_buf + (128 + gid)*CT2 + kk + 2*t4);
                b[0] = __float_as_uint(y.x);
                b[1] = __float_as_uint(y.y);
                mma8(dks[0], a[0], b);
                mma8(dks[1], a[1], b);
            }
        }
    }

    if (db == 1 && t4 == 0) {
        #pragma unroll
        for (int ia = 0; ia < 2; ia++) {
            int l = lb*32 + ia*16 + gid;
            dinv[l]     = 1.0f / dks[ia][0];
            dinv[l + 8] = 1.0f / dks[ia][2];
        }
    }
    __syncthreads();

    float* og = out + ((size_t)bh*LTOT + lt*TL2)*DD;
    #pragma unroll
    for (int ia = 0; ia < 2; ia++)
        #pragma unroll
        for (int nb = 0; nb < 8; nb++) {
            int l0 = lb*32 + ia*16 + gid;
            int d  = db*64 + nb*8 + 2*t4;
            float i0 = dinv[l0], i1 = dinv[l0 + 8];
            *(float2*)&og[l0*DD + d]       = make_float2(oacc[ia][nb][0]*i0, oacc[ia][nb][1]*i0);
            *(float2*)&og[(l0 + 8)*DD + d] = make_float2(oacc[ia][nb][2]*i1, oacc[ia][nb][3]*i1);
        }
}

extern "C" void kernel_launch(void* const* d_in, const int* in_sizes, int n_in,
                              void* d_out, int out_size) {
    const float* q    = (const float*)d_in[0];
    const float* k    = (const float*)d_in[1];
    const float* v    = (const float*)d_in[2];
    const float* proj = (const float*)d_in[3];
    float* out = (float*)d_out;

    size_t smem1 = (TL*LDX1 + TM*LDX1 + TM*PT1 + 64) * sizeof(float);                // ~86.3 KB
    size_t smem2 = (TL2*LDX2 + TM*LDXP + 136*CT2 + TL2*CT2 + TL2 + TL2) * sizeof(float); // ~183.6 KB
    cudaFuncSetAttribute(k1_ctx_kernel, cudaFuncAttributeMaxDynamicSharedMemorySize, (int)smem1);
    cudaFuncSetAttribute(k2_out_kernel, cudaFuncAttributeMaxDynamicSharedMemorySize, (int)smem2);

    kprep_kernel<<<(MM*DD/8 + 255) / 256, 256>>>(proj);
    k1_ctx_kernel<<<BH * NMT * NSPL, 256, smem1>>>(k, v, proj);
    kred_kernel<<<(N8CTX + N4KS) / 256, 256>>>();
    k2_out_kernel<<<BH * NLT2, 256, smem2>>>(q, proj, out);
}